// round 1
// baseline (speedup 1.0000x reference)
#include <cuda_runtime.h>
#include <math.h>

// ---------------- problem constants ----------------
#define BB   16
#define SS   256
#define NVV  196
#define DD   768
#define FFD  2048
#define VOC  30522
#define NL   6
#define NHH  8
#define HDIM 96
#define MQ   (BB*SS)          // 4096 query rows
#define MKV  (BB*NVV)         // 3136 memory rows
#define BHH  (BB*NHH)         // 128 batch*heads
#define MDEC (BB*(SS-1))      // 4080 decoded rows

// ---------------- scratch (static device memory; no allocations) ----------------
__device__ float g_x  [MQ*DD];
__device__ float g_tmp[MQ*3*DD];        // qkv / (q | kv) staging
__device__ float g_qh [BHH*SS*HDIM];
__device__ float g_kh [BHH*SS*HDIM];
__device__ float g_vh [BHH*SS*HDIM];
__device__ float g_sc [BHH*SS*SS];      // attention scores / probs
__device__ float g_oh [BHH*SS*HDIM];
__device__ float g_att[MQ*DD];
__device__ float g_y  [MQ*DD];
__device__ float g_ff [MQ*FFD];
__device__ float g_dec[MDEC*DD];

// ---------------- reductions (256-thread blocks) ----------------
__device__ __forceinline__ float blk_sum256(float v) {
    __shared__ float sh[8];
    #pragma unroll
    for (int o = 16; o > 0; o >>= 1) v += __shfl_xor_sync(0xffffffffu, v, o);
    __syncthreads();
    if ((threadIdx.x & 31) == 0) sh[threadIdx.x >> 5] = v;
    __syncthreads();
    float r = sh[0];
    #pragma unroll
    for (int i = 1; i < 8; i++) r += sh[i];
    return r;
}

__device__ __forceinline__ float blk_max256(float v) {
    __shared__ float sh[8];
    #pragma unroll
    for (int o = 16; o > 0; o >>= 1) v = fmaxf(v, __shfl_xor_sync(0xffffffffu, v, o));
    __syncthreads();
    if ((threadIdx.x & 31) == 0) sh[threadIdx.x >> 5] = v;
    __syncthreads();
    float r = sh[0];
    #pragma unroll
    for (int i = 1; i < 8; i++) r = fmaxf(r, sh[i]);
    return r;
}

// ---------------- main dense GEMM: C[M,N] = A[M,K] * B[N,K]^T (+bias)(+relu) ----------------
// 128x128 tile, BK=8, 256 threads, 8x8 micro-tile per thread.
__global__ __launch_bounds__(256) void gemm_nt(
    const float* __restrict__ A, const float* __restrict__ Bm,
    const float* __restrict__ bias, float* __restrict__ C,
    int M, int N, int K, int relu)
{
    __shared__ float As[8][128];
    __shared__ float Bs[8][128];
    const int tid = threadIdx.x;
    const int m0 = blockIdx.y * 128;
    const int n0 = blockIdx.x * 128;
    const int lr = tid >> 1;          // 0..127 (tile row for loads)
    const int lc = (tid & 1) << 2;    // 0 or 4 (k offset for float4 load)
    const int ty = tid >> 4;          // 0..15
    const int tx = tid & 15;          // 0..15

    float acc[8][8];
    #pragma unroll
    for (int i = 0; i < 8; i++)
        #pragma unroll
        for (int j = 0; j < 8; j++) acc[i][j] = 0.f;

    for (int k0 = 0; k0 < K; k0 += 8) {
        float4 av = make_float4(0.f,0.f,0.f,0.f);
        float4 bv = make_float4(0.f,0.f,0.f,0.f);
        int am = m0 + lr;
        if (am < M) av = *(const float4*)(A  + (size_t)am*K + k0 + lc);
        int bn = n0 + lr;
        if (bn < N) bv = *(const float4*)(Bm + (size_t)bn*K + k0 + lc);
        As[lc+0][lr] = av.x; As[lc+1][lr] = av.y; As[lc+2][lr] = av.z; As[lc+3][lr] = av.w;
        Bs[lc+0][lr] = bv.x; Bs[lc+1][lr] = bv.y; Bs[lc+2][lr] = bv.z; Bs[lc+3][lr] = bv.w;
        __syncthreads();
        #pragma unroll
        for (int kk = 0; kk < 8; kk++) {
            float a[8], b[8];
            #pragma unroll
            for (int i = 0; i < 8; i++) a[i] = As[kk][ty*8 + i];
            #pragma unroll
            for (int j = 0; j < 8; j++) b[j] = Bs[kk][tx*8 + j];
            #pragma unroll
            for (int i = 0; i < 8; i++)
                #pragma unroll
                for (int j = 0; j < 8; j++)
                    acc[i][j] += a[i]*b[j];
        }
        __syncthreads();
    }

    #pragma unroll
    for (int i = 0; i < 8; i++) {
        int m = m0 + ty*8 + i;
        if (m >= M) continue;
        #pragma unroll
        for (int j = 0; j < 8; j++) {
            int n = n0 + tx*8 + j;
            if (n >= N) continue;
            float v = acc[i][j];
            if (bias) v += bias[n];
            if (relu) v = fmaxf(v, 0.f);
            C[(size_t)m*N + n] = v;
        }
    }
}

// ---------------- batched scores: C[z] = (Q[z] * K[z]^T) * scale ----------------
// per-batch Q: Lq x 96, K: Lk x 96.  64x64 tile, BK=16, 4x4 micro.
__global__ __launch_bounds__(256) void bgemm_nt_scaled(
    const float* __restrict__ Q, const float* __restrict__ Km,
    float* __restrict__ Cc, int Lq, int Lk, float scale)
{
    __shared__ float As[16][64];
    __shared__ float Bs[16][64];
    const int z = blockIdx.z;
    const float* Qb = Q  + (size_t)z*Lq*HDIM;
    const float* Kb = Km + (size_t)z*Lk*HDIM;
    float* Cb = Cc + (size_t)z*Lq*Lk;
    const int q0 = blockIdx.y * 64;
    const int c0 = blockIdx.x * 64;
    const int tid = threadIdx.x;
    const int lr = tid >> 2;          // 0..63
    const int lc = (tid & 3) << 2;    // 0,4,8,12
    const int ty = tid >> 4, tx = tid & 15;

    float acc[4][4];
    #pragma unroll
    for (int i = 0; i < 4; i++)
        #pragma unroll
        for (int j = 0; j < 4; j++) acc[i][j] = 0.f;

    for (int k0 = 0; k0 < HDIM; k0 += 16) {
        float4 av = make_float4(0.f,0.f,0.f,0.f);
        float4 bv = make_float4(0.f,0.f,0.f,0.f);
        int qm = q0 + lr;
        if (qm < Lq) av = *(const float4*)(Qb + (size_t)qm*HDIM + k0 + lc);
        int kn = c0 + lr;
        if (kn < Lk) bv = *(const float4*)(Kb + (size_t)kn*HDIM + k0 + lc);
        As[lc+0][lr] = av.x; As[lc+1][lr] = av.y; As[lc+2][lr] = av.z; As[lc+3][lr] = av.w;
        Bs[lc+0][lr] = bv.x; Bs[lc+1][lr] = bv.y; Bs[lc+2][lr] = bv.z; Bs[lc+3][lr] = bv.w;
        __syncthreads();
        #pragma unroll
        for (int kk = 0; kk < 16; kk++) {
            float a[4], b[4];
            #pragma unroll
            for (int i = 0; i < 4; i++) a[i] = As[kk][ty*4 + i];
            #pragma unroll
            for (int j = 0; j < 4; j++) b[j] = Bs[kk][tx*4 + j];
            #pragma unroll
            for (int i = 0; i < 4; i++)
                #pragma unroll
                for (int j = 0; j < 4; j++)
                    acc[i][j] += a[i]*b[j];
        }
        __syncthreads();
    }
    #pragma unroll
    for (int i = 0; i < 4; i++) {
        int q = q0 + ty*4 + i;
        if (q >= Lq) continue;
        #pragma unroll
        for (int j = 0; j < 4; j++) {
            int c = c0 + tx*4 + j;
            if (c < Lk) Cb[(size_t)q*Lk + c] = acc[i][j] * scale;
        }
    }
}

// ---------------- batched PV: O[z] = P[z] (Lq x Lk) * V[z] (Lk x 96) ----------------
// 64 rows x 96 cols tile, BK=16, 4x6 micro.
__global__ __launch_bounds__(256) void bgemm_nn_av(
    const float* __restrict__ P, const float* __restrict__ Vv,
    float* __restrict__ O, int Lq, int Lk)
{
    __shared__ float Ps[16][64];
    __shared__ float Vs[16][HDIM];
    const int z = blockIdx.z;
    const float* Pb = P  + (size_t)z*Lq*Lk;
    const float* Vb = Vv + (size_t)z*Lk*HDIM;
    float* Ob = O + (size_t)z*Lq*HDIM;
    const int m0 = blockIdx.y * 64;
    const int tid = threadIdx.x;
    const int lr = tid >> 2;          // 0..63
    const int lc = (tid & 3) << 2;    // 0,4,8,12
    const int ty = tid >> 4, tx = tid & 15;

    float acc[4][6];
    #pragma unroll
    for (int i = 0; i < 4; i++)
        #pragma unroll
        for (int j = 0; j < 6; j++) acc[i][j] = 0.f;

    for (int k0 = 0; k0 < Lk; k0 += 16) {
        // P tile 64x16
        float4 pv = make_float4(0.f,0.f,0.f,0.f);
        {
            int pm = m0 + lr;
            int kc = k0 + lc;
            if (pm < Lq) {
                if (kc + 3 < Lk) {
                    pv = *(const float4*)(Pb + (size_t)pm*Lk + kc);
                } else {
                    float t[4] = {0.f,0.f,0.f,0.f};
                    #pragma unroll
                    for (int e = 0; e < 4; e++)
                        if (kc + e < Lk) t[e] = Pb[(size_t)pm*Lk + kc + e];
                    pv = make_float4(t[0],t[1],t[2],t[3]);
                }
            }
        }
        Ps[lc+0][lr] = pv.x; Ps[lc+1][lr] = pv.y; Ps[lc+2][lr] = pv.z; Ps[lc+3][lr] = pv.w;
        // V tile 16x96 (1536 elems, 6 per thread)
        #pragma unroll
        for (int i = 0; i < 6; i++) {
            int idx = tid*6 + i;
            int r = idx / HDIM, c = idx - r*HDIM;
            float v = 0.f;
            if (k0 + r < Lk) v = Vb[(size_t)(k0 + r)*HDIM + c];
            Vs[r][c] = v;
        }
        __syncthreads();
        #pragma unroll
        for (int kk = 0; kk < 16; kk++) {
            float a[4], b[6];
            #pragma unroll
            for (int i = 0; i < 4; i++) a[i] = Ps[kk][ty*4 + i];
            #pragma unroll
            for (int j = 0; j < 6; j++) b[j] = Vs[kk][tx*6 + j];
            #pragma unroll
            for (int i = 0; i < 4; i++)
                #pragma unroll
                for (int j = 0; j < 6; j++)
                    acc[i][j] += a[i]*b[j];
        }
        __syncthreads();
    }
    #pragma unroll
    for (int i = 0; i < 4; i++) {
        int m = m0 + ty*4 + i;
        if (m >= Lq) continue;
        #pragma unroll
        for (int j = 0; j < 6; j++)
            Ob[(size_t)m*HDIM + tx*6 + j] = acc[i][j];
    }
}

// ---------------- elementwise / softmax / LN ----------------
__global__ void add_pe_kernel(const float* __restrict__ te) {
    int idx = blockIdx.x*blockDim.x + threadIdx.x;
    if (idx >= MQ*DD) return;
    int d = idx % DD;
    int s = (idx / DD) % SS;
    int i2 = d & ~1;
    const float kfac = 9.210340371976184f / (float)DD;  // ln(10000)/D
    float div = expf(-(float)i2 * kfac);
    float ang = (float)s * div;
    float pe = (d & 1) ? cosf(ang) : sinf(ang);
    g_x[idx] = te[idx] + pe;
}

__global__ __launch_bounds__(256) void softmax_attn_kernel(float* __restrict__ sc, int Lq, int Lk, int causal) {
    int row = blockIdx.x;               // BHH*Lq rows
    int q = row % Lq;
    float* p = sc + (size_t)row * Lk;
    int t = threadIdx.x;
    float val = -3.0e38f;
    if (t < Lk) {
        val = p[t];
        if (causal && t > q) val = -1e9f;
    }
    float mx = blk_max256(val);
    float e = 0.f;
    if (t < Lk) e = expf(val - mx);
    float s = blk_sum256(e);
    if (t < Lk) p[t] = e / s;
}

__global__ __launch_bounds__(256) void add_ln_kernel(const float* __restrict__ y,
                                                     const float* __restrict__ w,
                                                     const float* __restrict__ b) {
    int r = blockIdx.x;                 // MQ rows
    int t = threadIdx.x;
    float vs[3];
    float s = 0.f;
    #pragma unroll
    for (int i = 0; i < 3; i++) {
        int c = t + i*256;
        vs[i] = g_x[(size_t)r*DD + c] + y[(size_t)r*DD + c];
        s += vs[i];
    }
    float mean = blk_sum256(s) * (1.f/DD);
    float ss = 0.f;
    #pragma unroll
    for (int i = 0; i < 3; i++) { float d0 = vs[i] - mean; ss += d0*d0; }
    float var = blk_sum256(ss) * (1.f/DD);
    float inv = rsqrtf(var + 1e-5f);
    #pragma unroll
    for (int i = 0; i < 3; i++) {
        int c = t + i*256;
        g_x[(size_t)r*DD + c] = (vs[i] - mean)*inv*w[c] + b[c];
    }
}

__global__ __launch_bounds__(256) void softmax_d_kernel(float* __restrict__ out) {
    int r = blockIdx.x;                 // MDEC rows
    int t = threadIdx.x;
    const float* p = g_dec + (size_t)r*DD;
    float vs[3]; float m = -3.0e38f;
    #pragma unroll
    for (int i = 0; i < 3; i++) { vs[i] = p[t + i*256]; m = fmaxf(m, vs[i]); }
    float mx = blk_max256(m);
    float s = 0.f;
    #pragma unroll
    for (int i = 0; i < 3; i++) { vs[i] = expf(vs[i] - mx); s += vs[i]; }
    float sum = blk_sum256(s);
    #pragma unroll
    for (int i = 0; i < 3; i++)
        out[(size_t)r*DD + t + i*256] = vs[i] / sum;
}

// ---------------- pack / unpack ----------------
__global__ void pack_self_kernel() {
    int idx = blockIdx.x*blockDim.x + threadIdx.x;
    if (idx >= BHH*SS*HDIM) return;
    int d = idx % HDIM;
    int s = (idx / HDIM) % SS;
    int z = idx / (SS*HDIM);
    int b = z / NHH, h = z % NHH;
    size_t src = ((size_t)(b*SS + s))*(3*DD) + h*HDIM + d;
    g_qh[idx] = g_tmp[src];
    g_kh[idx] = g_tmp[src + DD];
    g_vh[idx] = g_tmp[src + 2*DD];
}

__global__ void pack_q_kernel() {
    int idx = blockIdx.x*blockDim.x + threadIdx.x;
    if (idx >= BHH*SS*HDIM) return;
    int d = idx % HDIM;
    int s = (idx / HDIM) % SS;
    int z = idx / (SS*HDIM);
    int b = z / NHH, h = z % NHH;
    g_qh[idx] = g_tmp[((size_t)(b*SS + s))*DD + h*HDIM + d];
}

__global__ void pack_kv_kernel() {
    int idx = blockIdx.x*blockDim.x + threadIdx.x;
    if (idx >= BHH*NVV*HDIM) return;
    int d = idx % HDIM;
    int s = (idx / HDIM) % NVV;
    int z = idx / (NVV*HDIM);
    int b = z / NHH, h = z % NHH;
    size_t src = (size_t)MQ*DD + ((size_t)(b*NVV + s))*(2*DD) + h*HDIM + d;
    g_kh[idx] = g_tmp[src];
    g_vh[idx] = g_tmp[src + DD];
}

__global__ void unpack_o_kernel(int Lq) {
    int idx = blockIdx.x*blockDim.x + threadIdx.x;
    if (idx >= BHH*SS*HDIM) return;
    int d = idx % HDIM;
    int s = (idx / HDIM) % SS;
    int z = idx / (SS*HDIM);
    int b = z / NHH, h = z % NHH;
    g_att[((size_t)(b*SS + s))*DD + h*HDIM + d] = g_oh[idx];
    (void)Lq;
}

__global__ void copy_dec_kernel() {
    int idx = blockIdx.x*blockDim.x + threadIdx.x;
    if (idx >= MDEC*DD) return;
    int c = idx % DD;
    int r = idx / DD;
    int b = r / (SS-1);
    int s = r % (SS-1);
    g_dec[idx] = g_x[((size_t)(b*SS + s))*DD + c];
}

// ---------------- host orchestration ----------------
static inline dim3 gemm_grid(int M, int N) { return dim3((N + 127)/128, (M + 127)/128); }

extern "C" void kernel_launch(void* const* d_in, const int* in_sizes, int n_in,
                              void* d_out, int out_size) {
    (void)in_sizes; (void)n_in; (void)out_size;
    const float* fv          = (const float*)d_in[0];
    const float* te          = (const float*)d_in[1];
    const float* self_in_w   = (const float*)d_in[2];
    const float* self_in_b   = (const float*)d_in[3];
    const float* self_out_w  = (const float*)d_in[4];
    const float* self_out_b  = (const float*)d_in[5];
    const float* cross_in_w  = (const float*)d_in[6];
    const float* cross_in_b  = (const float*)d_in[7];
    const float* cross_out_w = (const float*)d_in[8];
    const float* cross_out_b = (const float*)d_in[9];
    const float* lin1_w      = (const float*)d_in[10];
    const float* lin1_b      = (const float*)d_in[11];
    const float* lin2_w      = (const float*)d_in[12];
    const float* lin2_b      = (const float*)d_in[13];
    const float* ln_w        = (const float*)d_in[14];
    const float* ln_b        = (const float*)d_in[15];
    const float* fc_out_w    = (const float*)d_in[16];
    float* out = (float*)d_out;

    float *x, *tmp, *qh, *kh, *vh, *sc, *vo, *att, *y, *ff, *dec;
    cudaGetSymbolAddress((void**)&x,   g_x);
    cudaGetSymbolAddress((void**)&tmp, g_tmp);
    cudaGetSymbolAddress((void**)&qh,  g_qh);
    cudaGetSymbolAddress((void**)&kh,  g_kh);
    cudaGetSymbolAddress((void**)&vh,  g_vh);
    cudaGetSymbolAddress((void**)&sc,  g_sc);
    cudaGetSymbolAddress((void**)&vo,  g_oh);
    cudaGetSymbolAddress((void**)&att, g_att);
    cudaGetSymbolAddress((void**)&y,   g_y);
    cudaGetSymbolAddress((void**)&ff,  g_ff);
    cudaGetSymbolAddress((void**)&dec, g_dec);

    const float scale = 0.1020620726159658f;   // 1/sqrt(96)

    // x = target_embed + PE
    add_pe_kernel<<<(MQ*DD + 255)/256, 256>>>(te);

    for (int l = 0; l < NL; l++) {
        const float* siw = self_in_w   + (size_t)l*3*DD*DD;
        const float* sib = self_in_b   + (size_t)l*3*DD;
        const float* sow = self_out_w  + (size_t)l*DD*DD;
        const float* sob = self_out_b  + (size_t)l*DD;
        const float* ciw = cross_in_w  + (size_t)l*3*DD*DD;
        const float* cib = cross_in_b  + (size_t)l*3*DD;
        const float* cow = cross_out_w + (size_t)l*DD*DD;
        const float* cob = cross_out_b + (size_t)l*DD;
        const float* l1w = lin1_w + (size_t)l*FFD*DD;
        const float* l1b = lin1_b + (size_t)l*FFD;
        const float* l2w = lin2_w + (size_t)l*DD*FFD;
        const float* l2b = lin2_b + (size_t)l*DD;

        // ---- self attention ----
        gemm_nt<<<gemm_grid(MQ, 3*DD), 256>>>(x, siw, sib, tmp, MQ, 3*DD, DD, 0);
        pack_self_kernel<<<(BHH*SS*HDIM + 255)/256, 256>>>();
        bgemm_nt_scaled<<<dim3(4, 4, BHH), 256>>>(qh, kh, sc, SS, SS, scale);
        softmax_attn_kernel<<<BHH*SS, 256>>>(sc, SS, SS, 1);
        bgemm_nn_av<<<dim3(1, 4, BHH), 256>>>(sc, vh, vo, SS, SS);
        unpack_o_kernel<<<(BHH*SS*HDIM + 255)/256, 256>>>(SS);
        gemm_nt<<<gemm_grid(MQ, DD), 256>>>(att, sow, sob, y, MQ, DD, DD, 0);
        add_ln_kernel<<<MQ, 256>>>(y, ln_w + (size_t)(l*3 + 0)*DD, ln_b + (size_t)(l*3 + 0)*DD);

        // ---- cross attention ----
        gemm_nt<<<gemm_grid(MQ, DD), 256>>>(x, ciw, cib, tmp, MQ, DD, DD, 0);
        pack_q_kernel<<<(BHH*SS*HDIM + 255)/256, 256>>>();
        gemm_nt<<<gemm_grid(MKV, 2*DD), 256>>>(fv, ciw + (size_t)DD*DD, cib + DD,
                                               tmp + (size_t)MQ*DD, MKV, 2*DD, DD, 0);
        pack_kv_kernel<<<(BHH*NVV*HDIM + 255)/256, 256>>>();
        bgemm_nt_scaled<<<dim3((NVV + 63)/64, 4, BHH), 256>>>(qh, kh, sc, SS, NVV, scale);
        softmax_attn_kernel<<<BHH*SS, 256>>>(sc, SS, NVV, 0);
        bgemm_nn_av<<<dim3(1, 4, BHH), 256>>>(sc, vh, vo, SS, NVV);
        unpack_o_kernel<<<(BHH*SS*HDIM + 255)/256, 256>>>(SS);
        gemm_nt<<<gemm_grid(MQ, DD), 256>>>(att, cow, cob, y, MQ, DD, DD, 0);
        add_ln_kernel<<<MQ, 256>>>(y, ln_w + (size_t)(l*3 + 1)*DD, ln_b + (size_t)(l*3 + 1)*DD);

        // ---- FFN ----
        gemm_nt<<<gemm_grid(MQ, FFD), 256>>>(x, l1w, l1b, ff, MQ, FFD, DD, 1);
        gemm_nt<<<gemm_grid(MQ, DD), 256>>>(ff, l2w, l2b, y, MQ, DD, FFD, 0);
        add_ln_kernel<<<MQ, 256>>>(y, ln_w + (size_t)(l*3 + 2)*DD, ln_b + (size_t)(l*3 + 2)*DD);
    }

    // ---- outputs: logits then F_t ----
    copy_dec_kernel<<<(MDEC*DD + 255)/256, 256>>>();
    gemm_nt<<<gemm_grid(MDEC, VOC), 256>>>(dec, fc_out_w, nullptr, out, MDEC, VOC, DD, 0);
    softmax_d_kernel<<<MDEC, 256>>>(out + (size_t)MDEC*VOC);
}

// round 2
// speedup vs baseline: 1.5457x; 1.5457x over previous
#include <cuda_runtime.h>
#include <math.h>

// ---------------- problem constants ----------------
#define BB   16
#define SS   256
#define NVV  196
#define DD   768
#define FFD  2048
#define VOC  30522
#define NL   6
#define NHH  8
#define HDIM 96
#define MQ   (BB*SS)          // 4096 query rows
#define MKV  (BB*NVV)         // 3136 memory rows
#define BHH  (BB*NHH)         // 128 batch*heads
#define MDEC (BB*(SS-1))      // 4080 decoded rows

// ---------------- scratch (static device memory; no allocations) ----------------
__device__ float g_x  [MQ*DD];
__device__ float g_tmp[MQ*3*DD];        // qkv / (q | kv) staging
__device__ float g_qh [BHH*SS*HDIM];
__device__ float g_kh [BHH*SS*HDIM];
__device__ float g_vh [BHH*SS*HDIM];
__device__ float g_sc [BHH*SS*SS];      // attention scores / probs
__device__ float g_oh [BHH*SS*HDIM];
__device__ float g_att[MQ*DD];
__device__ float g_y  [MQ*DD];
__device__ float g_ff [MQ*FFD];
__device__ float g_dec[MDEC*DD];

// ---------------- reductions (256-thread blocks) ----------------
__device__ __forceinline__ float blk_sum256(float v) {
    __shared__ float sh[8];
    #pragma unroll
    for (int o = 16; o > 0; o >>= 1) v += __shfl_xor_sync(0xffffffffu, v, o);
    __syncthreads();
    if ((threadIdx.x & 31) == 0) sh[threadIdx.x >> 5] = v;
    __syncthreads();
    float r = sh[0];
    #pragma unroll
    for (int i = 1; i < 8; i++) r += sh[i];
    return r;
}

__device__ __forceinline__ float blk_max256(float v) {
    __shared__ float sh[8];
    #pragma unroll
    for (int o = 16; o > 0; o >>= 1) v = fmaxf(v, __shfl_xor_sync(0xffffffffu, v, o));
    __syncthreads();
    if ((threadIdx.x & 31) == 0) sh[threadIdx.x >> 5] = v;
    __syncthreads();
    float r = sh[0];
    #pragma unroll
    for (int i = 1; i < 8; i++) r = fmaxf(r, sh[i]);
    return r;
}

// ---------------- tf32 helpers ----------------
__device__ __forceinline__ unsigned f2tf32(float f) {
    unsigned u;
    asm("cvt.rna.tf32.f32 %0, %1;" : "=r"(u) : "f"(f));
    return u;
}

__device__ __forceinline__ void mma_tf32(float (&d)[4], const unsigned (&a)[4], const unsigned (&b)[2]) {
    asm volatile(
        "mma.sync.aligned.m16n8k8.row.col.f32.tf32.tf32.f32 "
        "{%0,%1,%2,%3}, {%4,%5,%6,%7}, {%8,%9}, {%0,%1,%2,%3};\n"
        : "+f"(d[0]), "+f"(d[1]), "+f"(d[2]), "+f"(d[3])
        : "r"(a[0]), "r"(a[1]), "r"(a[2]), "r"(a[3]), "r"(b[0]), "r"(b[1]));
}

// ---------------- main dense GEMM (tensor cores, tf32) ----------------
// C[M,N] = A[M,K] * B[N,K]^T (+bias)(+relu)
// 128x128 block tile, BK=16, 256 threads (8 warps), warp tile 32x64.
// smem layout: row-major [row][k], stride SK=20 words (conflict-free frag LDS).
#define SK 20

__global__ __launch_bounds__(256) void gemm_nt_tf32(
    const float* __restrict__ A, const float* __restrict__ Bm,
    const float* __restrict__ bias, float* __restrict__ C,
    int M, int N, int K, int relu)
{
    __shared__ unsigned As[128*SK];
    __shared__ unsigned Bs[128*SK];
    const int tid  = threadIdx.x;
    const int m0   = blockIdx.y * 128;
    const int n0   = blockIdx.x * 128;
    const int lane = tid & 31;
    const int wid  = tid >> 5;
    const int wm   = (wid & 3) * 32;   // warp M offset
    const int wn   = (wid >> 2) * 64;  // warp N offset
    const int g    = lane >> 2;        // 0..7
    const int t    = lane & 3;         // 0..3

    // loader: idx = it*256 + tid; row = idx>>2 (0..127 over 2 iters), kc = (idx&3)*4
    const int lrow = tid >> 2;         // 0..63
    const int lkc  = (tid & 3) * 4;

    float acc[2][8][4];
    #pragma unroll
    for (int mi = 0; mi < 2; mi++)
        #pragma unroll
        for (int ni = 0; ni < 8; ni++)
            #pragma unroll
            for (int e = 0; e < 4; e++) acc[mi][ni][e] = 0.f;

    const float4 f40 = make_float4(0.f,0.f,0.f,0.f);
    float4 pa[2], pb[2];

    // prefetch tile 0
    #pragma unroll
    for (int it = 0; it < 2; it++) {
        int row = lrow + it*64;
        int am = m0 + row;
        pa[it] = (am < M) ? *(const float4*)(A  + (size_t)am*K + lkc) : f40;
        int bn = n0 + row;
        pb[it] = (bn < N) ? *(const float4*)(Bm + (size_t)bn*K + lkc) : f40;
    }

    for (int k0 = 0; k0 < K; k0 += 16) {
        // store prefetched tile to smem (tf32-rounded)
        #pragma unroll
        for (int it = 0; it < 2; it++) {
            int row = lrow + it*64;
            uint4 ua, ub;
            ua.x = f2tf32(pa[it].x); ua.y = f2tf32(pa[it].y);
            ua.z = f2tf32(pa[it].z); ua.w = f2tf32(pa[it].w);
            ub.x = f2tf32(pb[it].x); ub.y = f2tf32(pb[it].y);
            ub.z = f2tf32(pb[it].z); ub.w = f2tf32(pb[it].w);
            *(uint4*)(&As[row*SK + lkc]) = ua;
            *(uint4*)(&Bs[row*SK + lkc]) = ub;
        }
        __syncthreads();

        // prefetch next tile
        int kn = k0 + 16;
        if (kn < K) {
            #pragma unroll
            for (int it = 0; it < 2; it++) {
                int row = lrow + it*64;
                int am = m0 + row;
                pa[it] = (am < M) ? *(const float4*)(A  + (size_t)am*K + kn + lkc) : f40;
                int bn = n0 + row;
                pb[it] = (bn < N) ? *(const float4*)(Bm + (size_t)bn*K + kn + lkc) : f40;
            }
        }

        // compute: 2 k8-steps
        #pragma unroll
        for (int s = 0; s < 2; s++) {
            const int ks = s*8;
            unsigned a[2][4], b[8][2];
            #pragma unroll
            for (int mi = 0; mi < 2; mi++) {
                int r = wm + mi*16 + g;
                a[mi][0] = As[(r    )*SK + ks + t];
                a[mi][1] = As[(r + 8)*SK + ks + t];
                a[mi][2] = As[(r    )*SK + ks + t + 4];
                a[mi][3] = As[(r + 8)*SK + ks + t + 4];
            }
            #pragma unroll
            for (int ni = 0; ni < 8; ni++) {
                int c = wn + ni*8 + g;
                b[ni][0] = Bs[c*SK + ks + t];
                b[ni][1] = Bs[c*SK + ks + t + 4];
            }
            #pragma unroll
            for (int mi = 0; mi < 2; mi++)
                #pragma unroll
                for (int ni = 0; ni < 8; ni++)
                    mma_tf32(acc[mi][ni], a[mi], b[ni]);
        }
        __syncthreads();
    }

    // epilogue
    #pragma unroll
    for (int mi = 0; mi < 2; mi++) {
        #pragma unroll
        for (int half = 0; half < 2; half++) {
            int r = m0 + wm + mi*16 + g + half*8;
            if (r >= M) continue;
            #pragma unroll
            for (int ni = 0; ni < 8; ni++) {
                int c = n0 + wn + ni*8 + 2*t;
                if (c >= N) continue;
                float v0 = acc[mi][ni][half*2 + 0];
                float v1 = acc[mi][ni][half*2 + 1];
                if (bias) { v0 += bias[c]; if (c+1 < N) v1 += bias[c+1]; }
                if (relu) { v0 = fmaxf(v0, 0.f); v1 = fmaxf(v1, 0.f); }
                if (c + 1 < N) {
                    *(float2*)(C + (size_t)r*N + c) = make_float2(v0, v1);
                } else {
                    C[(size_t)r*N + c] = v0;
                }
            }
        }
    }
}

// ---------------- batched scores: C[z] = (Q[z] * K[z]^T) * scale ----------------
__global__ __launch_bounds__(256) void bgemm_nt_scaled(
    const float* __restrict__ Q, const float* __restrict__ Km,
    float* __restrict__ Cc, int Lq, int Lk, float scale)
{
    __shared__ float As[16][64];
    __shared__ float Bs[16][64];
    const int z = blockIdx.z;
    const float* Qb = Q  + (size_t)z*Lq*HDIM;
    const float* Kb = Km + (size_t)z*Lk*HDIM;
    float* Cb = Cc + (size_t)z*Lq*Lk;
    const int q0 = blockIdx.y * 64;
    const int c0 = blockIdx.x * 64;
    const int tid = threadIdx.x;
    const int lr = tid >> 2;
    const int lc = (tid & 3) << 2;
    const int ty = tid >> 4, tx = tid & 15;

    float acc[4][4];
    #pragma unroll
    for (int i = 0; i < 4; i++)
        #pragma unroll
        for (int j = 0; j < 4; j++) acc[i][j] = 0.f;

    for (int k0 = 0; k0 < HDIM; k0 += 16) {
        float4 av = make_float4(0.f,0.f,0.f,0.f);
        float4 bv = make_float4(0.f,0.f,0.f,0.f);
        int qm = q0 + lr;
        if (qm < Lq) av = *(const float4*)(Qb + (size_t)qm*HDIM + k0 + lc);
        int kn = c0 + lr;
        if (kn < Lk) bv = *(const float4*)(Kb + (size_t)kn*HDIM + k0 + lc);
        As[lc+0][lr] = av.x; As[lc+1][lr] = av.y; As[lc+2][lr] = av.z; As[lc+3][lr] = av.w;
        Bs[lc+0][lr] = bv.x; Bs[lc+1][lr] = bv.y; Bs[lc+2][lr] = bv.z; Bs[lc+3][lr] = bv.w;
        __syncthreads();
        #pragma unroll
        for (int kk = 0; kk < 16; kk++) {
            float a[4], b[4];
            #pragma unroll
            for (int i = 0; i < 4; i++) a[i] = As[kk][ty*4 + i];
            #pragma unroll
            for (int j = 0; j < 4; j++) b[j] = Bs[kk][tx*4 + j];
            #pragma unroll
            for (int i = 0; i < 4; i++)
                #pragma unroll
                for (int j = 0; j < 4; j++)
                    acc[i][j] += a[i]*b[j];
        }
        __syncthreads();
    }
    #pragma unroll
    for (int i = 0; i < 4; i++) {
        int q = q0 + ty*4 + i;
        if (q >= Lq) continue;
        #pragma unroll
        for (int j = 0; j < 4; j++) {
            int c = c0 + tx*4 + j;
            if (c < Lk) Cb[(size_t)q*Lk + c] = acc[i][j] * scale;
        }
    }
}

// ---------------- batched PV: O[z] = P[z] (Lq x Lk) * V[z] (Lk x 96) ----------------
__global__ __launch_bounds__(256) void bgemm_nn_av(
    const float* __restrict__ P, const float* __restrict__ Vv,
    float* __restrict__ O, int Lq, int Lk)
{
    __shared__ float Ps[16][64];
    __shared__ float Vs[16][HDIM];
    const int z = blockIdx.z;
    const float* Pb = P  + (size_t)z*Lq*Lk;
    const float* Vb = Vv + (size_t)z*Lk*HDIM;
    float* Ob = O + (size_t)z*Lq*HDIM;
    const int m0 = blockIdx.y * 64;
    const int tid = threadIdx.x;
    const int lr = tid >> 2;
    const int lc = (tid & 3) << 2;
    const int ty = tid >> 4, tx = tid & 15;

    float acc[4][6];
    #pragma unroll
    for (int i = 0; i < 4; i++)
        #pragma unroll
        for (int j = 0; j < 6; j++) acc[i][j] = 0.f;

    for (int k0 = 0; k0 < Lk; k0 += 16) {
        float4 pv = make_float4(0.f,0.f,0.f,0.f);
        {
            int pm = m0 + lr;
            int kc = k0 + lc;
            if (pm < Lq) {
                if (kc + 3 < Lk) {
                    pv = *(const float4*)(Pb + (size_t)pm*Lk + kc);
                } else {
                    float tt[4] = {0.f,0.f,0.f,0.f};
                    #pragma unroll
                    for (int e = 0; e < 4; e++)
                        if (kc + e < Lk) tt[e] = Pb[(size_t)pm*Lk + kc + e];
                    pv = make_float4(tt[0],tt[1],tt[2],tt[3]);
                }
            }
        }
        Ps[lc+0][lr] = pv.x; Ps[lc+1][lr] = pv.y; Ps[lc+2][lr] = pv.z; Ps[lc+3][lr] = pv.w;
        #pragma unroll
        for (int i = 0; i < 6; i++) {
            int idx = tid*6 + i;
            int r = idx / HDIM, c = idx - r*HDIM;
            float v = 0.f;
            if (k0 + r < Lk) v = Vb[(size_t)(k0 + r)*HDIM + c];
            Vs[r][c] = v;
        }
        __syncthreads();
        #pragma unroll
        for (int kk = 0; kk < 16; kk++) {
            float a[4], b[6];
            #pragma unroll
            for (int i = 0; i < 4; i++) a[i] = Ps[kk][ty*4 + i];
            #pragma unroll
            for (int j = 0; j < 6; j++) b[j] = Vs[kk][tx*6 + j];
            #pragma unroll
            for (int i = 0; i < 4; i++)
                #pragma unroll
                for (int j = 0; j < 6; j++)
                    acc[i][j] += a[i]*b[j];
        }
        __syncthreads();
    }
    #pragma unroll
    for (int i = 0; i < 4; i++) {
        int m = m0 + ty*4 + i;
        if (m >= Lq) continue;
        #pragma unroll
        for (int j = 0; j < 6; j++)
            Ob[(size_t)m*HDIM + tx*6 + j] = acc[i][j];
    }
}

// ---------------- elementwise / softmax / LN ----------------
__global__ void add_pe_kernel(const float* __restrict__ te) {
    int idx = blockIdx.x*blockDim.x + threadIdx.x;
    if (idx >= MQ*DD) return;
    int d = idx % DD;
    int s = (idx / DD) % SS;
    int i2 = d & ~1;
    const float kfac = 9.210340371976184f / (float)DD;  // ln(10000)/D
    float div = expf(-(float)i2 * kfac);
    float ang = (float)s * div;
    float pe = (d & 1) ? cosf(ang) : sinf(ang);
    g_x[idx] = te[idx] + pe;
}

__global__ __launch_bounds__(256) void softmax_attn_kernel(float* __restrict__ sc, int Lq, int Lk, int causal) {
    int row = blockIdx.x;
    int q = row % Lq;
    float* p = sc + (size_t)row * Lk;
    int t = threadIdx.x;
    float val = -3.0e38f;
    if (t < Lk) {
        val = p[t];
        if (causal && t > q) val = -1e9f;
    }
    float mx = blk_max256(val);
    float e = 0.f;
    if (t < Lk) e = expf(val - mx);
    float s = blk_sum256(e);
    if (t < Lk) p[t] = e / s;
}

__global__ __launch_bounds__(256) void add_ln_kernel(const float* __restrict__ y,
                                                     const float* __restrict__ w,
                                                     const float* __restrict__ b) {
    int r = blockIdx.x;
    int t = threadIdx.x;
    float vs[3];
    float s = 0.f;
    #pragma unroll
    for (int i = 0; i < 3; i++) {
        int c = t + i*256;
        vs[i] = g_x[(size_t)r*DD + c] + y[(size_t)r*DD + c];
        s += vs[i];
    }
    float mean = blk_sum256(s) * (1.f/DD);
    float ss = 0.f;
    #pragma unroll
    for (int i = 0; i < 3; i++) { float d0 = vs[i] - mean; ss += d0*d0; }
    float var = blk_sum256(ss) * (1.f/DD);
    float inv = rsqrtf(var + 1e-5f);
    #pragma unroll
    for (int i = 0; i < 3; i++) {
        int c = t + i*256;
        g_x[(size_t)r*DD + c] = (vs[i] - mean)*inv*w[c] + b[c];
    }
}

__global__ __launch_bounds__(256) void softmax_d_kernel(float* __restrict__ out) {
    int r = blockIdx.x;
    int t = threadIdx.x;
    const float* p = g_dec + (size_t)r*DD;
    float vs[3]; float m = -3.0e38f;
    #pragma unroll
    for (int i = 0; i < 3; i++) { vs[i] = p[t + i*256]; m = fmaxf(m, vs[i]); }
    float mx = blk_max256(m);
    float s = 0.f;
    #pragma unroll
    for (int i = 0; i < 3; i++) { vs[i] = expf(vs[i] - mx); s += vs[i]; }
    float sum = blk_sum256(s);
    #pragma unroll
    for (int i = 0; i < 3; i++)
        out[(size_t)r*DD + t + i*256] = vs[i] / sum;
}

// ---------------- pack / unpack ----------------
__global__ void pack_self_kernel() {
    int idx = blockIdx.x*blockDim.x + threadIdx.x;
    if (idx >= BHH*SS*HDIM) return;
    int d = idx % HDIM;
    int s = (idx / HDIM) % SS;
    int z = idx / (SS*HDIM);
    int b = z / NHH, h = z % NHH;
    size_t src = ((size_t)(b*SS + s))*(3*DD) + h*HDIM + d;
    g_qh[idx] = g_tmp[src];
    g_kh[idx] = g_tmp[src + DD];
    g_vh[idx] = g_tmp[src + 2*DD];
}

__global__ void pack_q_kernel() {
    int idx = blockIdx.x*blockDim.x + threadIdx.x;
    if (idx >= BHH*SS*HDIM) return;
    int d = idx % HDIM;
    int s = (idx / HDIM) % SS;
    int z = idx / (SS*HDIM);
    int b = z / NHH, h = z % NHH;
    g_qh[idx] = g_tmp[((size_t)(b*SS + s))*DD + h*HDIM + d];
}

__global__ void pack_kv_kernel() {
    int idx = blockIdx.x*blockDim.x + threadIdx.x;
    if (idx >= BHH*NVV*HDIM) return;
    int d = idx % HDIM;
    int s = (idx / HDIM) % NVV;
    int z = idx / (NVV*HDIM);
    int b = z / NHH, h = z % NHH;
    size_t src = (size_t)MQ*DD + ((size_t)(b*NVV + s))*(2*DD) + h*HDIM + d;
    g_kh[idx] = g_tmp[src];
    g_vh[idx] = g_tmp[src + DD];
}

__global__ void unpack_o_kernel(int Lq) {
    int idx = blockIdx.x*blockDim.x + threadIdx.x;
    if (idx >= BHH*SS*HDIM) return;
    int d = idx % HDIM;
    int s = (idx / HDIM) % SS;
    int z = idx / (SS*HDIM);
    int b = z / NHH, h = z % NHH;
    g_att[((size_t)(b*SS + s))*DD + h*HDIM + d] = g_oh[idx];
    (void)Lq;
}

__global__ void copy_dec_kernel() {
    int idx = blockIdx.x*blockDim.x + threadIdx.x;
    if (idx >= MDEC*DD) return;
    int c = idx % DD;
    int r = idx / DD;
    int b = r / (SS-1);
    int s = r % (SS-1);
    g_dec[idx] = g_x[((size_t)(b*SS + s))*DD + c];
}

// ---------------- host orchestration ----------------
static inline dim3 gemm_grid(int M, int N) { return dim3((N + 127)/128, (M + 127)/128); }

extern "C" void kernel_launch(void* const* d_in, const int* in_sizes, int n_in,
                              void* d_out, int out_size) {
    (void)in_sizes; (void)n_in; (void)out_size;
    const float* fv          = (const float*)d_in[0];
    const float* te          = (const float*)d_in[1];
    const float* self_in_w   = (const float*)d_in[2];
    const float* self_in_b   = (const float*)d_in[3];
    const float* self_out_w  = (const float*)d_in[4];
    const float* self_out_b  = (const float*)d_in[5];
    const float* cross_in_w  = (const float*)d_in[6];
    const float* cross_in_b  = (const float*)d_in[7];
    const float* cross_out_w = (const float*)d_in[8];
    const float* cross_out_b = (const float*)d_in[9];
    const float* lin1_w      = (const float*)d_in[10];
    const float* lin1_b      = (const float*)d_in[11];
    const float* lin2_w      = (const float*)d_in[12];
    const float* lin2_b      = (const float*)d_in[13];
    const float* ln_w        = (const float*)d_in[14];
    const float* ln_b        = (const float*)d_in[15];
    const float* fc_out_w    = (const float*)d_in[16];
    float* out = (float*)d_out;

    float *x, *tmp, *qh, *kh, *vh, *sc, *vo, *att, *y, *ff, *dec;
    cudaGetSymbolAddress((void**)&x,   g_x);
    cudaGetSymbolAddress((void**)&tmp, g_tmp);
    cudaGetSymbolAddress((void**)&qh,  g_qh);
    cudaGetSymbolAddress((void**)&kh,  g_kh);
    cudaGetSymbolAddress((void**)&vh,  g_vh);
    cudaGetSymbolAddress((void**)&sc,  g_sc);
    cudaGetSymbolAddress((void**)&vo,  g_oh);
    cudaGetSymbolAddress((void**)&att, g_att);
    cudaGetSymbolAddress((void**)&y,   g_y);
    cudaGetSymbolAddress((void**)&ff,  g_ff);
    cudaGetSymbolAddress((void**)&dec, g_dec);

    const float scale = 0.1020620726159658f;   // 1/sqrt(96)

    add_pe_kernel<<<(MQ*DD + 255)/256, 256>>>(te);

    for (int l = 0; l < NL; l++) {
        const float* siw = self_in_w   + (size_t)l*3*DD*DD;
        const float* sib = self_in_b   + (size_t)l*3*DD;
        const float* sow = self_out_w  + (size_t)l*DD*DD;
        const float* sob = self_out_b  + (size_t)l*DD;
        const float* ciw = cross_in_w  + (size_t)l*3*DD*DD;
        const float* cib = cross_in_b  + (size_t)l*3*DD;
        const float* cow = cross_out_w + (size_t)l*DD*DD;
        const float* cob = cross_out_b + (size_t)l*DD;
        const float* l1w = lin1_w + (size_t)l*FFD*DD;
        const float* l1b = lin1_b + (size_t)l*FFD;
        const float* l2w = lin2_w + (size_t)l*DD*FFD;
        const float* l2b = lin2_b + (size_t)l*DD;

        // ---- self attention ----
        gemm_nt_tf32<<<gemm_grid(MQ, 3*DD), 256>>>(x, siw, sib, tmp, MQ, 3*DD, DD, 0);
        pack_self_kernel<<<(BHH*SS*HDIM + 255)/256, 256>>>();
        bgemm_nt_scaled<<<dim3(4, 4, BHH), 256>>>(qh, kh, sc, SS, SS, scale);
        softmax_attn_kernel<<<BHH*SS, 256>>>(sc, SS, SS, 1);
        bgemm_nn_av<<<dim3(1, 4, BHH), 256>>>(sc, vh, vo, SS, SS);
        unpack_o_kernel<<<(BHH*SS*HDIM + 255)/256, 256>>>(SS);
        gemm_nt_tf32<<<gemm_grid(MQ, DD), 256>>>(att, sow, sob, y, MQ, DD, DD, 0);
        add_ln_kernel<<<MQ, 256>>>(y, ln_w + (size_t)(l*3 + 0)*DD, ln_b + (size_t)(l*3 + 0)*DD);

        // ---- cross attention ----
        gemm_nt_tf32<<<gemm_grid(MQ, DD), 256>>>(x, ciw, cib, tmp, MQ, DD, DD, 0);
        pack_q_kernel<<<(BHH*SS*HDIM + 255)/256, 256>>>();
        gemm_nt_tf32<<<gemm_grid(MKV, 2*DD), 256>>>(fv, ciw + (size_t)DD*DD, cib + DD,
                                                    tmp + (size_t)MQ*DD, MKV, 2*DD, DD, 0);
        pack_kv_kernel<<<(BHH*NVV*HDIM + 255)/256, 256>>>();
        bgemm_nt_scaled<<<dim3((NVV + 63)/64, 4, BHH), 256>>>(qh, kh, sc, SS, NVV, scale);
        softmax_attn_kernel<<<BHH*SS, 256>>>(sc, SS, NVV, 0);
        bgemm_nn_av<<<dim3(1, 4, BHH), 256>>>(sc, vh, vo, SS, NVV);
        unpack_o_kernel<<<(BHH*SS*HDIM + 255)/256, 256>>>(SS);
        gemm_nt_tf32<<<gemm_grid(MQ, DD), 256>>>(att, cow, cob, y, MQ, DD, DD, 0);
        add_ln_kernel<<<MQ, 256>>>(y, ln_w + (size_t)(l*3 + 1)*DD, ln_b + (size_t)(l*3 + 1)*DD);

        // ---- FFN ----
        gemm_nt_tf32<<<gemm_grid(MQ, FFD), 256>>>(x, l1w, l1b, ff, MQ, FFD, DD, 1);
        gemm_nt_tf32<<<gemm_grid(MQ, DD), 256>>>(ff, l2w, l2b, y, MQ, DD, FFD, 0);
        add_ln_kernel<<<MQ, 256>>>(y, ln_w + (size_t)(l*3 + 2)*DD, ln_b + (size_t)(l*3 + 2)*DD);
    }

    // ---- outputs: logits then F_t ----
    copy_dec_kernel<<<(MDEC*DD + 255)/256, 256>>>();
    gemm_nt_tf32<<<gemm_grid(MDEC, VOC), 256>>>(dec, fc_out_w, nullptr, out, MDEC, VOC, DD, 0);
    softmax_d_kernel<<<MDEC, 256>>>(out + (size_t)MDEC*VOC);
}

// round 5
// speedup vs baseline: 2.7520x; 1.7804x over previous
#include <cuda_runtime.h>
#include <math.h>
#include <stdint.h>

// ---------------- problem constants ----------------
#define BB   16
#define SS   256
#define NVV  196
#define DD   768
#define FFD  2048
#define VOC  30522
#define NL   6
#define NHH  8
#define HDIM 96
#define MQ   (BB*SS)          // 4096 query rows
#define MKV  (BB*NVV)         // 3136 memory rows
#define BHH  (BB*NHH)         // 128 batch*heads
#define MDEC (BB*(SS-1))      // 4080 decoded rows

// ---------------- scratch (static device memory; no allocations) ----------------
__device__ float g_x  [MQ*DD];
__device__ float g_tmp[MQ*3*DD];
__device__ float g_qh [BHH*SS*HDIM];
__device__ float g_kh [BHH*SS*HDIM];
__device__ float g_vh [BHH*SS*HDIM];
__device__ float g_sc [BHH*SS*SS];
__device__ float g_oh [BHH*SS*HDIM];
__device__ float g_att[MQ*DD];
__device__ float g_y  [MQ*DD];
__device__ float g_ff [MQ*FFD];
__device__ float g_dec[MDEC*DD];

// ---------------- reductions (256-thread blocks) ----------------
__device__ __forceinline__ float blk_sum256(float v) {
    __shared__ float sh[8];
    #pragma unroll
    for (int o = 16; o > 0; o >>= 1) v += __shfl_xor_sync(0xffffffffu, v, o);
    __syncthreads();
    if ((threadIdx.x & 31) == 0) sh[threadIdx.x >> 5] = v;
    __syncthreads();
    float r = sh[0];
    #pragma unroll
    for (int i = 1; i < 8; i++) r += sh[i];
    return r;
}

__device__ __forceinline__ float blk_max256(float v) {
    __shared__ float sh[8];
    #pragma unroll
    for (int o = 16; o > 0; o >>= 1) v = fmaxf(v, __shfl_xor_sync(0xffffffffu, v, o));
    __syncthreads();
    if ((threadIdx.x & 31) == 0) sh[threadIdx.x >> 5] = v;
    __syncthreads();
    float r = sh[0];
    #pragma unroll
    for (int i = 1; i < 8; i++) r = fmaxf(r, sh[i]);
    return r;
}

// ---------------- tf32 / mma helpers ----------------
__device__ __forceinline__ unsigned f2tf32(float f) {
    unsigned u;
    asm("cvt.rna.tf32.f32 %0, %1;" : "=r"(u) : "f"(f));
    return u;
}

__device__ __forceinline__ void mma_tf32(float (&d)[4], const unsigned (&a)[4], const unsigned (&b)[2]) {
    asm volatile(
        "mma.sync.aligned.m16n8k8.row.col.f32.tf32.tf32.f32 "
        "{%0,%1,%2,%3}, {%4,%5,%6,%7}, {%8,%9}, {%0,%1,%2,%3};\n"
        : "+f"(d[0]), "+f"(d[1]), "+f"(d[2]), "+f"(d[3])
        : "r"(a[0]), "r"(a[1]), "r"(a[2]), "r"(a[3]), "r"(b[0]), "r"(b[1]));
}

__device__ __forceinline__ void ldsm4(unsigned &d0, unsigned &d1, unsigned &d2, unsigned &d3, uint32_t a) {
    asm volatile("ldmatrix.sync.aligned.m8n8.x4.shared.b16 {%0,%1,%2,%3}, [%4];"
                 : "=r"(d0), "=r"(d1), "=r"(d2), "=r"(d3) : "r"(a));
}

__device__ __forceinline__ uint32_t smem_u32(const void* p) {
    uint32_t a;
    asm("{ .reg .u64 t; cvta.to.shared.u64 t, %1; cvt.u32.u64 %0, t; }" : "=r"(a) : "l"(p));
    return a;
}

// ---------------- main dense GEMM (mma.sync tf32, ldmatrix, double-buffered) ----------------
// C[M,N] = A[M,K] * B[N,K]^T (+bias)(+relu).  K % 16 == 0.
// 128x128 tile, BK=16, 256 threads (8 warps), warp tile 32x64.
#define SK 20   // smem row stride in words; conflict-free for ldmatrix (20r mod 32 all distinct)

__global__ __launch_bounds__(256, 2) void gemm_nt_tf32(
    const float* __restrict__ A, const float* __restrict__ Bm,
    const float* __restrict__ bias, float* __restrict__ C,
    int M, int N, int K, int relu)
{
    __shared__ unsigned As[2][128*SK];
    __shared__ unsigned Bs[2][128*SK];
    const int tid  = threadIdx.x;
    const int lane = tid & 31;
    const int wid  = tid >> 5;
    const int m0   = blockIdx.y * 128;
    const int n0   = blockIdx.x * 128;
    const int wm   = (wid & 3) * 32;
    const int wn   = (wid >> 2) * 64;
    const int g    = lane >> 2;
    const int t    = lane & 3;

    // ldmatrix per-lane offsets (in words)
    // A x4: lanes0-7 rows0-7 k+0 | 8-15 rows8-15 k+0 | 16-23 rows0-7 k+4 | 24-31 rows8-15 k+4
    const int aoff = ((lane & 7) + ((lane >> 3) & 1) * 8) * SK + ((lane >> 4) & 1) * 4;
    // B x4: lanes0-7 n0-7 k+0 | 8-15 n0-7 k+4 | 16-23 n8-15 k+0 | 24-31 n8-15 k+4
    const int boff = ((lane & 7) + ((lane >> 4) & 1) * 8) * SK + ((lane >> 3) & 1) * 4;

    const uint32_t Asm = smem_u32(&As[0][0]);
    const uint32_t Bsm = smem_u32(&Bs[0][0]);

    float acc[2][8][4];
    #pragma unroll
    for (int mi = 0; mi < 2; mi++)
        #pragma unroll
        for (int ni = 0; ni < 8; ni++)
            #pragma unroll
            for (int e = 0; e < 4; e++) acc[mi][ni][e] = 0.f;

    const float4 f40 = make_float4(0.f, 0.f, 0.f, 0.f);
    float4 ra[2], rb[2];
    const int lrow0 = tid >> 2;          // 0..63
    const int lq    = (tid & 3) * 4;     // k word offset 0,4,8,12

    // ---- prologue: load chunk 0 ----
    #pragma unroll
    for (int it = 0; it < 2; it++) {
        int row = lrow0 + it*64;
        int gm = m0 + row;
        ra[it] = (gm < M) ? *(const float4*)(A  + (size_t)gm*K + lq) : f40;
        int gn = n0 + row;
        rb[it] = (gn < N) ? *(const float4*)(Bm + (size_t)gn*K + lq) : f40;
    }
    #pragma unroll
    for (int it = 0; it < 2; it++) {
        int row = lrow0 + it*64;
        uint4 ua, ub;
        ua.x = f2tf32(ra[it].x); ua.y = f2tf32(ra[it].y); ua.z = f2tf32(ra[it].z); ua.w = f2tf32(ra[it].w);
        ub.x = f2tf32(rb[it].x); ub.y = f2tf32(rb[it].y); ub.z = f2tf32(rb[it].z); ub.w = f2tf32(rb[it].w);
        *(uint4*)&As[0][row*SK + lq] = ua;
        *(uint4*)&Bs[0][row*SK + lq] = ub;
    }
    __syncthreads();

    const int NC = K >> 4;
    for (int c = 0; c < NC; c++) {
        const int cur = c & 1;
        const bool have_next = (c + 1 < NC);

        // prefetch next chunk from gmem
        if (have_next) {
            const int k0 = (c + 1) << 4;
            #pragma unroll
            for (int it = 0; it < 2; it++) {
                int row = lrow0 + it*64;
                int gm = m0 + row;
                ra[it] = (gm < M) ? *(const float4*)(A  + (size_t)gm*K + k0 + lq) : f40;
                int gn = n0 + row;
                rb[it] = (gn < N) ? *(const float4*)(Bm + (size_t)gn*K + k0 + lq) : f40;
            }
        }

        // compute on stage cur
        const uint32_t Acur = Asm + (uint32_t)(cur * (128*SK*4));
        const uint32_t Bcur = Bsm + (uint32_t)(cur * (128*SK*4));
        #pragma unroll
        for (int ks = 0; ks < 16; ks += 8) {
            unsigned a[2][4], b[8][2];
            #pragma unroll
            for (int mi = 0; mi < 2; mi++)
                ldsm4(a[mi][0], a[mi][1], a[mi][2], a[mi][3],
                      Acur + (uint32_t)(((wm + mi*16)*SK + ks + aoff) * 4));
            #pragma unroll
            for (int nj = 0; nj < 4; nj++)
                ldsm4(b[2*nj][0], b[2*nj][1], b[2*nj+1][0], b[2*nj+1][1],
                      Bcur + (uint32_t)(((wn + nj*16)*SK + ks + boff) * 4));
            #pragma unroll
            for (int mi = 0; mi < 2; mi++)
                #pragma unroll
                for (int ni = 0; ni < 8; ni++)
                    mma_tf32(acc[mi][ni], a[mi], b[ni]);
        }

        // store next chunk into the other stage
        if (have_next) {
            const int nxt = cur ^ 1;
            #pragma unroll
            for (int it = 0; it < 2; it++) {
                int row = lrow0 + it*64;
                uint4 ua, ub;
                ua.x = f2tf32(ra[it].x); ua.y = f2tf32(ra[it].y); ua.z = f2tf32(ra[it].z); ua.w = f2tf32(ra[it].w);
                ub.x = f2tf32(rb[it].x); ub.y = f2tf32(rb[it].y); ub.z = f2tf32(rb[it].z); ub.w = f2tf32(rb[it].w);
                *(uint4*)&As[nxt][row*SK + lq] = ua;
                *(uint4*)&Bs[nxt][row*SK + lq] = ub;
            }
        }
        __syncthreads();
    }

    // ---- epilogue ----
    #pragma unroll
    for (int mi = 0; mi < 2; mi++) {
        #pragma unroll
        for (int half = 0; half < 2; half++) {
            int r = m0 + wm + mi*16 + g + half*8;
            if (r >= M) continue;
            #pragma unroll
            for (int ni = 0; ni < 8; ni++) {
                int cn = n0 + wn + ni*8 + 2*t;
                if (cn >= N) continue;
                float v0 = acc[mi][ni][half*2 + 0];
                float v1 = acc[mi][ni][half*2 + 1];
                if (bias) { v0 += bias[cn]; if (cn+1 < N) v1 += bias[cn+1]; }
                if (relu) { v0 = fmaxf(v0, 0.f); v1 = fmaxf(v1, 0.f); }
                if (cn + 1 < N) {
                    *(float2*)(C + (size_t)r*N + cn) = make_float2(v0, v1);
                } else {
                    C[(size_t)r*N + cn] = v0;
                }
            }
        }
    }
}

// ---------------- batched scores: C[z] = (Q[z] * K[z]^T) * scale ----------------
__global__ __launch_bounds__(256) void bgemm_nt_scaled(
    const float* __restrict__ Q, const float* __restrict__ Km,
    float* __restrict__ Cc, int Lq, int Lk, float scale)
{
    __shared__ float As[16][64];
    __shared__ float Bs[16][64];
    const int z = blockIdx.z;
    const float* Qb = Q  + (size_t)z*Lq*HDIM;
    const float* Kb = Km + (size_t)z*Lk*HDIM;
    float* Cb = Cc + (size_t)z*Lq*Lk;
    const int q0 = blockIdx.y * 64;
    const int c0 = blockIdx.x * 64;
    const int tid = threadIdx.x;
    const int lr = tid >> 2;
    const int lc = (tid & 3) << 2;
    const int ty = tid >> 4, tx = tid & 15;

    float acc[4][4];
    #pragma unroll
    for (int i = 0; i < 4; i++)
        #pragma unroll
        for (int j = 0; j < 4; j++) acc[i][j] = 0.f;

    for (int k0 = 0; k0 < HDIM; k0 += 16) {
        float4 av = make_float4(0.f,0.f,0.f,0.f);
        float4 bv = make_float4(0.f,0.f,0.f,0.f);
        int qm = q0 + lr;
        if (qm < Lq) av = *(const float4*)(Qb + (size_t)qm*HDIM + k0 + lc);
        int kn = c0 + lr;
        if (kn < Lk) bv = *(const float4*)(Kb + (size_t)kn*HDIM + k0 + lc);
        As[lc+0][lr] = av.x; As[lc+1][lr] = av.y; As[lc+2][lr] = av.z; As[lc+3][lr] = av.w;
        Bs[lc+0][lr] = bv.x; Bs[lc+1][lr] = bv.y; Bs[lc+2][lr] = bv.z; Bs[lc+3][lr] = bv.w;
        __syncthreads();
        #pragma unroll
        for (int kk = 0; kk < 16; kk++) {
            float a[4], b[4];
            #pragma unroll
            for (int i = 0; i < 4; i++) a[i] = As[kk][ty*4 + i];
            #pragma unroll
            for (int j = 0; j < 4; j++) b[j] = Bs[kk][tx*4 + j];
            #pragma unroll
            for (int i = 0; i < 4; i++)
                #pragma unroll
                for (int j = 0; j < 4; j++)
                    acc[i][j] += a[i]*b[j];
        }
        __syncthreads();
    }
    #pragma unroll
    for (int i = 0; i < 4; i++) {
        int q = q0 + ty*4 + i;
        if (q >= Lq) continue;
        #pragma unroll
        for (int j = 0; j < 4; j++) {
            int c = c0 + tx*4 + j;
            if (c < Lk) Cb[(size_t)q*Lk + c] = acc[i][j] * scale;
        }
    }
}

// ---------------- batched PV: O[z] = P[z] (Lq x Lk) * V[z] (Lk x 96) ----------------
__global__ __launch_bounds__(256) void bgemm_nn_av(
    const float* __restrict__ P, const float* __restrict__ Vv,
    float* __restrict__ O, int Lq, int Lk)
{
    __shared__ float Ps[16][64];
    __shared__ float Vs[16][HDIM];
    const int z = blockIdx.z;
    const float* Pb = P  + (size_t)z*Lq*Lk;
    const float* Vb = Vv + (size_t)z*Lk*HDIM;
    float* Ob = O + (size_t)z*Lq*HDIM;
    const int m0 = blockIdx.y * 64;
    const int tid = threadIdx.x;
    const int lr = tid >> 2;
    const int lc = (tid & 3) << 2;
    const int ty = tid >> 4, tx = tid & 15;

    float acc[4][6];
    #pragma unroll
    for (int i = 0; i < 4; i++)
        #pragma unroll
        for (int j = 0; j < 6; j++) acc[i][j] = 0.f;

    for (int k0 = 0; k0 < Lk; k0 += 16) {
        float4 pv = make_float4(0.f,0.f,0.f,0.f);
        {
            int pm = m0 + lr;
            int kc = k0 + lc;
            if (pm < Lq) {
                if (kc + 3 < Lk) {
                    pv = *(const float4*)(Pb + (size_t)pm*Lk + kc);
                } else {
                    float tt[4] = {0.f,0.f,0.f,0.f};
                    #pragma unroll
                    for (int e = 0; e < 4; e++)
                        if (kc + e < Lk) tt[e] = Pb[(size_t)pm*Lk + kc + e];
                    pv = make_float4(tt[0],tt[1],tt[2],tt[3]);
                }
            }
        }
        Ps[lc+0][lr] = pv.x; Ps[lc+1][lr] = pv.y; Ps[lc+2][lr] = pv.z; Ps[lc+3][lr] = pv.w;
        #pragma unroll
        for (int i = 0; i < 6; i++) {
            int idx = tid*6 + i;
            int r = idx / HDIM, c = idx - r*HDIM;
            float v = 0.f;
            if (k0 + r < Lk) v = Vb[(size_t)(k0 + r)*HDIM + c];
            Vs[r][c] = v;
        }
        __syncthreads();
        #pragma unroll
        for (int kk = 0; kk < 16; kk++) {
            float a[4], b[6];
            #pragma unroll
            for (int i = 0; i < 4; i++) a[i] = Ps[kk][ty*4 + i];
            #pragma unroll
            for (int j = 0; j < 6; j++) b[j] = Vs[kk][tx*6 + j];
            #pragma unroll
            for (int i = 0; i < 4; i++)
                #pragma unroll
                for (int j = 0; j < 6; j++)
                    acc[i][j] += a[i]*b[j];
        }
        __syncthreads();
    }
    #pragma unroll
    for (int i = 0; i < 4; i++) {
        int m = m0 + ty*4 + i;
        if (m >= Lq) continue;
        #pragma unroll
        for (int j = 0; j < 6; j++)
            Ob[(size_t)m*HDIM + tx*6 + j] = acc[i][j];
    }
}

// ---------------- elementwise / softmax / LN ----------------
__global__ void add_pe_kernel(const float* __restrict__ te) {
    int idx = blockIdx.x*blockDim.x + threadIdx.x;
    if (idx >= MQ*DD) return;
    int d = idx % DD;
    int s = (idx / DD) % SS;
    int i2 = d & ~1;
    const float kfac = 9.210340371976184f / (float)DD;
    float div = expf(-(float)i2 * kfac);
    float ang = (float)s * div;
    float pe = (d & 1) ? cosf(ang) : sinf(ang);
    g_x[idx] = te[idx] + pe;
}

__global__ __launch_bounds__(256) void softmax_attn_kernel(float* __restrict__ sc, int Lq, int Lk, int causal) {
    int row = blockIdx.x;
    int q = row % Lq;
    float* p = sc + (size_t)row * Lk;
    int t = threadIdx.x;
    float val = -3.0e38f;
    if (t < Lk) {
        val = p[t];
        if (causal && t > q) val = -1e9f;
    }
    float mx = blk_max256(val);
    float e = 0.f;
    if (t < Lk) e = expf(val - mx);
    float s = blk_sum256(e);
    if (t < Lk) p[t] = e / s;
}

__global__ __launch_bounds__(256) void add_ln_kernel(const float* __restrict__ y,
                                                     const float* __restrict__ w,
                                                     const float* __restrict__ b) {
    int r = blockIdx.x;
    int t = threadIdx.x;
    float vs[3];
    float s = 0.f;
    #pragma unroll
    for (int i = 0; i < 3; i++) {
        int c = t + i*256;
        vs[i] = g_x[(size_t)r*DD + c] + y[(size_t)r*DD + c];
        s += vs[i];
    }
    float mean = blk_sum256(s) * (1.f/DD);
    float ss = 0.f;
    #pragma unroll
    for (int i = 0; i < 3; i++) { float d0 = vs[i] - mean; ss += d0*d0; }
    float var = blk_sum256(ss) * (1.f/DD);
    float inv = rsqrtf(var + 1e-5f);
    #pragma unroll
    for (int i = 0; i < 3; i++) {
        int c = t + i*256;
        g_x[(size_t)r*DD + c] = (vs[i] - mean)*inv*w[c] + b[c];
    }
}

__global__ __launch_bounds__(256) void softmax_d_kernel(float* __restrict__ out) {
    int r = blockIdx.x;
    int t = threadIdx.x;
    const float* p = g_dec + (size_t)r*DD;
    float vs[3]; float m = -3.0e38f;
    #pragma unroll
    for (int i = 0; i < 3; i++) { vs[i] = p[t + i*256]; m = fmaxf(m, vs[i]); }
    float mx = blk_max256(m);
    float s = 0.f;
    #pragma unroll
    for (int i = 0; i < 3; i++) { vs[i] = expf(vs[i] - mx); s += vs[i]; }
    float sum = blk_sum256(s);
    #pragma unroll
    for (int i = 0; i < 3; i++)
        out[(size_t)r*DD + t + i*256] = vs[i] / sum;
}

// ---------------- pack / unpack ----------------
__global__ void pack_self_kernel() {
    int idx = blockIdx.x*blockDim.x + threadIdx.x;
    if (idx >= BHH*SS*HDIM) return;
    int d = idx % HDIM;
    int s = (idx / HDIM) % SS;
    int z = idx / (SS*HDIM);
    int b = z / NHH, h = z % NHH;
    size_t src = ((size_t)(b*SS + s))*(3*DD) + h*HDIM + d;
    g_qh[idx] = g_tmp[src];
    g_kh[idx] = g_tmp[src + DD];
    g_vh[idx] = g_tmp[src + 2*DD];
}

__global__ void pack_q_kernel() {
    int idx = blockIdx.x*blockDim.x + threadIdx.x;
    if (idx >= BHH*SS*HDIM) return;
    int d = idx % HDIM;
    int s = (idx / HDIM) % SS;
    int z = idx / (SS*HDIM);
    int b = z / NHH, h = z % NHH;
    g_qh[idx] = g_tmp[((size_t)(b*SS + s))*DD + h*HDIM + d];
}

__global__ void pack_kv_kernel() {
    int idx = blockIdx.x*blockDim.x + threadIdx.x;
    if (idx >= BHH*NVV*HDIM) return;
    int d = idx % HDIM;
    int s = (idx / HDIM) % NVV;
    int z = idx / (NVV*HDIM);
    int b = z / NHH, h = z % NHH;
    size_t src = (size_t)MQ*DD + ((size_t)(b*NVV + s))*(2*DD) + h*HDIM + d;
    g_kh[idx] = g_tmp[src];
    g_vh[idx] = g_tmp[src + DD];
}

__global__ void unpack_o_kernel() {
    int idx = blockIdx.x*blockDim.x + threadIdx.x;
    if (idx >= BHH*SS*HDIM) return;
    int d = idx % HDIM;
    int s = (idx / HDIM) % SS;
    int z = idx / (SS*HDIM);
    int b = z / NHH, h = z % NHH;
    g_att[((size_t)(b*SS + s))*DD + h*HDIM + d] = g_oh[idx];
}

__global__ void copy_dec_kernel() {
    int idx = blockIdx.x*blockDim.x + threadIdx.x;
    if (idx >= MDEC*DD) return;
    int c = idx % DD;
    int r = idx / DD;
    int b = r / (SS-1);
    int s = r % (SS-1);
    g_dec[idx] = g_x[((size_t)(b*SS + s))*DD + c];
}

// ---------------- host orchestration ----------------
static inline dim3 gemm_grid(int M, int N) { return dim3((N + 127)/128, (M + 127)/128); }

static void launch_gemm(const float* A, const float* B, const float* bias, float* C,
                        int M, int N, int K, int relu) {
    gemm_nt_tf32<<<gemm_grid(M, N), 256>>>(A, B, bias, C, M, N, K, relu);
}

extern "C" void kernel_launch(void* const* d_in, const int* in_sizes, int n_in,
                              void* d_out, int out_size) {
    (void)in_sizes; (void)n_in; (void)out_size;
    const float* fv          = (const float*)d_in[0];
    const float* te          = (const float*)d_in[1];
    const float* self_in_w   = (const float*)d_in[2];
    const float* self_in_b   = (const float*)d_in[3];
    const float* self_out_w  = (const float*)d_in[4];
    const float* self_out_b  = (const float*)d_in[5];
    const float* cross_in_w  = (const float*)d_in[6];
    const float* cross_in_b  = (const float*)d_in[7];
    const float* cross_out_w = (const float*)d_in[8];
    const float* cross_out_b = (const float*)d_in[9];
    const float* lin1_w      = (const float*)d_in[10];
    const float* lin1_b      = (const float*)d_in[11];
    const float* lin2_w      = (const float*)d_in[12];
    const float* lin2_b      = (const float*)d_in[13];
    const float* ln_w        = (const float*)d_in[14];
    const float* ln_b        = (const float*)d_in[15];
    const float* fc_out_w    = (const float*)d_in[16];
    float* out = (float*)d_out;

    float *x, *tmp, *qh, *kh, *vh, *sc, *vo, *att, *y, *ff, *dec;
    cudaGetSymbolAddress((void**)&x,   g_x);
    cudaGetSymbolAddress((void**)&tmp, g_tmp);
    cudaGetSymbolAddress((void**)&qh,  g_qh);
    cudaGetSymbolAddress((void**)&kh,  g_kh);
    cudaGetSymbolAddress((void**)&vh,  g_vh);
    cudaGetSymbolAddress((void**)&sc,  g_sc);
    cudaGetSymbolAddress((void**)&vo,  g_oh);
    cudaGetSymbolAddress((void**)&att, g_att);
    cudaGetSymbolAddress((void**)&y,   g_y);
    cudaGetSymbolAddress((void**)&ff,  g_ff);
    cudaGetSymbolAddress((void**)&dec, g_dec);

    const float scale = 0.1020620726159658f;   // 1/sqrt(96)

    add_pe_kernel<<<(MQ*DD + 255)/256, 256>>>(te);

    for (int l = 0; l < NL; l++) {
        const float* siw = self_in_w   + (size_t)l*3*DD*DD;
        const float* sib = self_in_b   + (size_t)l*3*DD;
        const float* sow = self_out_w  + (size_t)l*DD*DD;
        const float* sob = self_out_b  + (size_t)l*DD;
        const float* ciw = cross_in_w  + (size_t)l*3*DD*DD;
        const float* cib = cross_in_b  + (size_t)l*3*DD;
        const float* cow = cross_out_w + (size_t)l*DD*DD;
        const float* cob = cross_out_b + (size_t)l*DD;
        const float* l1w = lin1_w + (size_t)l*FFD*DD;
        const float* l1b = lin1_b + (size_t)l*FFD;
        const float* l2w = lin2_w + (size_t)l*DD*FFD;
        const float* l2b = lin2_b + (size_t)l*DD;

        // ---- self attention ----
        launch_gemm(x, siw, sib, tmp, MQ, 3*DD, DD, 0);
        pack_self_kernel<<<(BHH*SS*HDIM + 255)/256, 256>>>();
        bgemm_nt_scaled<<<dim3(4, 4, BHH), 256>>>(qh, kh, sc, SS, SS, scale);
        softmax_attn_kernel<<<BHH*SS, 256>>>(sc, SS, SS, 1);
        bgemm_nn_av<<<dim3(1, 4, BHH), 256>>>(sc, vh, vo, SS, SS);
        unpack_o_kernel<<<(BHH*SS*HDIM + 255)/256, 256>>>();
        launch_gemm(att, sow, sob, y, MQ, DD, DD, 0);
        add_ln_kernel<<<MQ, 256>>>(y, ln_w + (size_t)(l*3 + 0)*DD, ln_b + (size_t)(l*3 + 0)*DD);

        // ---- cross attention ----
        launch_gemm(x, ciw, cib, tmp, MQ, DD, DD, 0);
        pack_q_kernel<<<(BHH*SS*HDIM + 255)/256, 256>>>();
        launch_gemm(fv, ciw + (size_t)DD*DD, cib + DD, tmp + (size_t)MQ*DD, MKV, 2*DD, DD, 0);
        pack_kv_kernel<<<(BHH*NVV*HDIM + 255)/256, 256>>>();
        bgemm_nt_scaled<<<dim3((NVV + 63)/64, 4, BHH), 256>>>(qh, kh, sc, SS, NVV, scale);
        softmax_attn_kernel<<<BHH*SS, 256>>>(sc, SS, NVV, 0);
        bgemm_nn_av<<<dim3(1, 4, BHH), 256>>>(sc, vh, vo, SS, NVV);
        unpack_o_kernel<<<(BHH*SS*HDIM + 255)/256, 256>>>();
        launch_gemm(att, cow, cob, y, MQ, DD, DD, 0);
        add_ln_kernel<<<MQ, 256>>>(y, ln_w + (size_t)(l*3 + 1)*DD, ln_b + (size_t)(l*3 + 1)*DD);

        // ---- FFN ----
        launch_gemm(x, l1w, l1b, ff, MQ, FFD, DD, 1);
        launch_gemm(ff, l2w, l2b, y, MQ, DD, FFD, 0);
        add_ln_kernel<<<MQ, 256>>>(y, ln_w + (size_t)(l*3 + 2)*DD, ln_b + (size_t)(l*3 + 2)*DD);
    }

    // ---- outputs: logits then F_t ----
    copy_dec_kernel<<<(MDEC*DD + 255)/256, 256>>>();
    launch_gemm(dec, fc_out_w, nullptr, out, MDEC, VOC, DD, 0);
    softmax_d_kernel<<<MDEC, 256>>>(out + (size_t)MDEC*VOC);
}

// round 7
// speedup vs baseline: 3.5375x; 1.2855x over previous
#include <cuda_runtime.h>
#include <math.h>
#include <stdint.h>

// ---------------- problem constants ----------------
#define BB   16
#define SS   256
#define NVV  196
#define DD   768
#define FFD  2048
#define VOC  30522
#define NL   6
#define NHH  8
#define HDIM 96
#define MQ   (BB*SS)          // 4096 query rows
#define MKV  (BB*NVV)         // 3136 memory rows
#define BHH  (BB*NHH)         // 128 batch*heads
#define MDEC (BB*(SS-1))      // 4080 decoded rows

// ---------------- scratch (static device memory; no allocations) ----------------
__device__ float g_x  [MQ*DD];
__device__ float g_qh [BHH*SS*HDIM];
__device__ float g_kh [BHH*SS*HDIM];
__device__ float g_vh [BHH*SS*HDIM];
__device__ float g_att[MQ*DD];
__device__ float g_y  [MQ*DD];
__device__ float g_ff [MQ*FFD];
__device__ float g_dec[MDEC*DD];

// ---------------- reductions (256-thread blocks) ----------------
__device__ __forceinline__ float blk_sum256(float v) {
    __shared__ float sh[8];
    #pragma unroll
    for (int o = 16; o > 0; o >>= 1) v += __shfl_xor_sync(0xffffffffu, v, o);
    __syncthreads();
    if ((threadIdx.x & 31) == 0) sh[threadIdx.x >> 5] = v;
    __syncthreads();
    float r = sh[0];
    #pragma unroll
    for (int i = 1; i < 8; i++) r += sh[i];
    return r;
}

__device__ __forceinline__ float blk_max256(float v) {
    __shared__ float sh[8];
    #pragma unroll
    for (int o = 16; o > 0; o >>= 1) v = fmaxf(v, __shfl_xor_sync(0xffffffffu, v, o));
    __syncthreads();
    if ((threadIdx.x & 31) == 0) sh[threadIdx.x >> 5] = v;
    __syncthreads();
    float r = sh[0];
    #pragma unroll
    for (int i = 1; i < 8; i++) r = fmaxf(r, sh[i]);
    return r;
}

// ---------------- tf32 / mma helpers ----------------
__device__ __forceinline__ unsigned f2tf32(float f) {
    unsigned u;
    asm("cvt.rna.tf32.f32 %0, %1;" : "=r"(u) : "f"(f));
    return u;
}

__device__ __forceinline__ void mma_tf32(float (&d)[4], const unsigned (&a)[4], const unsigned (&b)[2]) {
    asm volatile(
        "mma.sync.aligned.m16n8k8.row.col.f32.tf32.tf32.f32 "
        "{%0,%1,%2,%3}, {%4,%5,%6,%7}, {%8,%9}, {%0,%1,%2,%3};\n"
        : "+f"(d[0]), "+f"(d[1]), "+f"(d[2]), "+f"(d[3])
        : "r"(a[0]), "r"(a[1]), "r"(a[2]), "r"(a[3]), "r"(b[0]), "r"(b[1]));
}

__device__ __forceinline__ void ldsm4(unsigned &d0, unsigned &d1, unsigned &d2, unsigned &d3, uint32_t a) {
    asm volatile("ldmatrix.sync.aligned.m8n8.x4.shared.b16 {%0,%1,%2,%3}, [%4];"
                 : "=r"(d0), "=r"(d1), "=r"(d2), "=r"(d3) : "r"(a));
}

__device__ __forceinline__ uint32_t smem_u32(const void* p) {
    uint32_t a;
    asm("{ .reg .u64 t; cvta.to.shared.u64 t, %1; cvt.u32.u64 %0, t; }" : "=r"(a) : "l"(p));
    return a;
}

// ---------------- main dense GEMM (mma.sync tf32, ldmatrix, double-buffered) ----------------
// C[M,N] = A[M,K] * B[N,K]^T (+bias)(+relu or head-pack scatter).  K % 16 == 0.
// mode 0: row-major C.  mode 1: QKV pack (N=2304, rows=b*SS+s).
// mode 2: Q pack (N=768). mode 3: KV pack (N=1536, rows=b*NVV+s).
#define SK 20

__global__ __launch_bounds__(256, 2) void gemm_nt_tf32(
    const float* __restrict__ A, const float* __restrict__ Bm,
    const float* __restrict__ bias, float* __restrict__ C,
    int M, int N, int K, int relu, int mode,
    float* __restrict__ dq, float* __restrict__ dk, float* __restrict__ dv)
{
    __shared__ unsigned As[2][128*SK];
    __shared__ unsigned Bs[2][128*SK];
    const int tid  = threadIdx.x;
    const int lane = tid & 31;
    const int wid  = tid >> 5;
    const int m0   = blockIdx.y * 128;
    const int n0   = blockIdx.x * 128;
    const int wm   = (wid & 3) * 32;
    const int wn   = (wid >> 2) * 64;
    const int g    = lane >> 2;
    const int t    = lane & 3;

    const int aoff = ((lane & 7) + ((lane >> 3) & 1) * 8) * SK + ((lane >> 4) & 1) * 4;
    const int boff = ((lane & 7) + ((lane >> 4) & 1) * 8) * SK + ((lane >> 3) & 1) * 4;

    const uint32_t Asm = smem_u32(&As[0][0]);
    const uint32_t Bsm = smem_u32(&Bs[0][0]);

    float acc[2][8][4];
    #pragma unroll
    for (int mi = 0; mi < 2; mi++)
        #pragma unroll
        for (int ni = 0; ni < 8; ni++)
            #pragma unroll
            for (int e = 0; e < 4; e++) acc[mi][ni][e] = 0.f;

    const float4 f40 = make_float4(0.f, 0.f, 0.f, 0.f);
    float4 ra[2], rb[2];
    const int lrow0 = tid >> 2;
    const int lq    = (tid & 3) * 4;

    #pragma unroll
    for (int it = 0; it < 2; it++) {
        int row = lrow0 + it*64;
        int gm = m0 + row;
        ra[it] = (gm < M) ? *(const float4*)(A  + (size_t)gm*K + lq) : f40;
        int gn = n0 + row;
        rb[it] = (gn < N) ? *(const float4*)(Bm + (size_t)gn*K + lq) : f40;
    }
    #pragma unroll
    for (int it = 0; it < 2; it++) {
        int row = lrow0 + it*64;
        uint4 ua, ub;
        ua.x = f2tf32(ra[it].x); ua.y = f2tf32(ra[it].y); ua.z = f2tf32(ra[it].z); ua.w = f2tf32(ra[it].w);
        ub.x = f2tf32(rb[it].x); ub.y = f2tf32(rb[it].y); ub.z = f2tf32(rb[it].z); ub.w = f2tf32(rb[it].w);
        *(uint4*)&As[0][row*SK + lq] = ua;
        *(uint4*)&Bs[0][row*SK + lq] = ub;
    }
    __syncthreads();

    const int NC = K >> 4;
    for (int c = 0; c < NC; c++) {
        const int cur = c & 1;
        const bool have_next = (c + 1 < NC);

        if (have_next) {
            const int k0 = (c + 1) << 4;
            #pragma unroll
            for (int it = 0; it < 2; it++) {
                int row = lrow0 + it*64;
                int gm = m0 + row;
                ra[it] = (gm < M) ? *(const float4*)(A  + (size_t)gm*K + k0 + lq) : f40;
                int gn = n0 + row;
                rb[it] = (gn < N) ? *(const float4*)(Bm + (size_t)gn*K + k0 + lq) : f40;
            }
        }

        const uint32_t Acur = Asm + (uint32_t)(cur * (128*SK*4));
        const uint32_t Bcur = Bsm + (uint32_t)(cur * (128*SK*4));
        #pragma unroll
        for (int ks = 0; ks < 16; ks += 8) {
            unsigned a[2][4], b[8][2];
            #pragma unroll
            for (int mi = 0; mi < 2; mi++)
                ldsm4(a[mi][0], a[mi][1], a[mi][2], a[mi][3],
                      Acur + (uint32_t)(((wm + mi*16)*SK + ks + aoff) * 4));
            #pragma unroll
            for (int nj = 0; nj < 4; nj++)
                ldsm4(b[2*nj][0], b[2*nj][1], b[2*nj+1][0], b[2*nj+1][1],
                      Bcur + (uint32_t)(((wn + nj*16)*SK + ks + boff) * 4));
            #pragma unroll
            for (int mi = 0; mi < 2; mi++)
                #pragma unroll
                for (int ni = 0; ni < 8; ni++)
                    mma_tf32(acc[mi][ni], a[mi], b[ni]);
        }

        if (have_next) {
            const int nxt = cur ^ 1;
            #pragma unroll
            for (int it = 0; it < 2; it++) {
                int row = lrow0 + it*64;
                uint4 ua, ub;
                ua.x = f2tf32(ra[it].x); ua.y = f2tf32(ra[it].y); ua.z = f2tf32(ra[it].z); ua.w = f2tf32(ra[it].w);
                ub.x = f2tf32(rb[it].x); ub.y = f2tf32(rb[it].y); ub.z = f2tf32(rb[it].z); ub.w = f2tf32(rb[it].w);
                *(uint4*)&As[nxt][row*SK + lq] = ua;
                *(uint4*)&Bs[nxt][row*SK + lq] = ub;
            }
        }
        __syncthreads();
    }

    // ---- epilogue ----
    #pragma unroll
    for (int mi = 0; mi < 2; mi++) {
        #pragma unroll
        for (int half = 0; half < 2; half++) {
            int r = m0 + wm + mi*16 + g + half*8;
            if (r >= M) continue;
            #pragma unroll
            for (int ni = 0; ni < 8; ni++) {
                int cn = n0 + wn + ni*8 + 2*t;
                if (cn >= N) continue;
                float v0 = acc[mi][ni][half*2 + 0];
                float v1 = acc[mi][ni][half*2 + 1];
                if (bias) { v0 += bias[cn]; if (cn+1 < N) v1 += bias[cn+1]; }
                if (mode == 0) {
                    if (relu) { v0 = fmaxf(v0, 0.f); v1 = fmaxf(v1, 0.f); }
                    if (cn + 1 < N) *(float2*)(C + (size_t)r*N + cn) = make_float2(v0, v1);
                    else            C[(size_t)r*N + cn] = v0;
                } else {
                    // head-pack scatter: fragments never cross 96-col head or 768-col section
                    int bb_, s_, which, rem, hh, dd;
                    float* base;
                    if (mode == 1) {         // self QKV, rows b*256+s
                        bb_ = r >> 8; s_ = r & 255;
                        which = cn / DD; rem = cn - which*DD;
                        hh = rem / HDIM; dd = rem - hh*HDIM;
                        base = (which == 0) ? dq : (which == 1) ? dk : dv;
                        base += (((size_t)((bb_<<3) + hh))*SS + s_)*HDIM + dd;
                    } else if (mode == 2) {  // cross Q
                        bb_ = r >> 8; s_ = r & 255;
                        hh = cn / HDIM; dd = cn - hh*HDIM;
                        base = dq + (((size_t)((bb_<<3) + hh))*SS + s_)*HDIM + dd;
                    } else {                 // cross KV, rows b*196+s
                        bb_ = r / NVV; s_ = r - bb_*NVV;
                        which = cn / DD; rem = cn - which*DD;
                        hh = rem / HDIM; dd = rem - hh*HDIM;
                        base = ((which == 0) ? dk : dv);
                        base += (((size_t)((bb_<<3) + hh))*NVV + s_)*HDIM + dd;
                    }
                    *(float2*)base = make_float2(v0, v1);
                }
            }
        }
    }
}

// ---------------- fused flash attention (tf32 mma) ----------------
// grid (SS/128, BHH). Block: 256 thr, 8 warps x 16 q-rows. K-tiles of 32 keys.
// Q,K,V packed [z][s][96]. Output written unpacked into Oatt[b*SS+s][h*96+d].
#define FA_SP  36
#define FA_SKK 100

__global__ __launch_bounds__(256) void flash_attn(
    const float* __restrict__ Qh, const float* __restrict__ Kh, const float* __restrict__ Vh,
    float* __restrict__ Oatt, int kvlen, int causal)
{
    __shared__ unsigned Ks[32*FA_SKK];     // 12.8 KB (K tile, [key][d] tf32)
    __shared__ unsigned Vs[96*FA_SP];      // 13.8 KB (V tile transposed, [d][key] tf32)
    __shared__ unsigned Ps[8][16*FA_SP];   // 18.4 KB (per-warp P staging)
    const int tid = threadIdx.x, w = tid >> 5, lane = tid & 31;
    const int g = lane >> 2, t = lane & 3;
    const int z = blockIdx.y;
    const int b = z >> 3, h = z & 7;
    const int q0 = blockIdx.x * 128;
    const float scale = 0.1020620726159658f;   // 1/sqrt(96)

    const float* Qb = Qh + ((size_t)z*SS + q0)*HDIM;
    const float* Kb = Kh + (size_t)z*kvlen*HDIM;
    const float* Vb = Vh + (size_t)z*kvlen*HDIM;

    // Q fragments in registers (scale folded in)
    unsigned qa[12][4];
    {
        const float* qr0 = Qb + (w*16 + g)*HDIM;
        const float* qr1 = qr0 + 8*HDIM;
        #pragma unroll
        for (int ks = 0; ks < 12; ks++) {
            qa[ks][0] = f2tf32(qr0[ks*8 + t] * scale);
            qa[ks][1] = f2tf32(qr1[ks*8 + t] * scale);
            qa[ks][2] = f2tf32(qr0[ks*8 + t + 4] * scale);
            qa[ks][3] = f2tf32(qr1[ks*8 + t + 4] * scale);
        }
    }

    float oacc[12][4];
    #pragma unroll
    for (int n = 0; n < 12; n++) { oacc[n][0]=0.f; oacc[n][1]=0.f; oacc[n][2]=0.f; oacc[n][3]=0.f; }
    float m0 = -1e30f, m1 = -1e30f, l0 = 0.f, l1 = 0.f;
    const int row0 = q0 + w*16 + g;
    const int row1 = row0 + 8;

    const uint32_t KsA = smem_u32(Ks);
    const uint32_t VsA = smem_u32(Vs);
    const uint32_t PsA = smem_u32(Ps[w]);
    const int boffK = ((lane & 7) + ((lane >> 4) & 1)*8)*FA_SKK + ((lane >> 3) & 1)*4;
    const int boffV = ((lane & 7) + ((lane >> 4) & 1)*8)*FA_SP  + ((lane >> 3) & 1)*4;
    const int aoffP = ((lane & 7) + ((lane >> 3) & 1)*8)*FA_SP  + ((lane >> 4) & 1)*4;

    int ntiles = (kvlen + 31) >> 5;
    if (causal) { int lim = ((q0 + 127) >> 5) + 1; if (lim < ntiles) ntiles = lim; }

    for (int j = 0; j < ntiles; j++) {
        const int k0 = j*32;

        // load K tile (coalesced reads, contiguous smem writes)
        #pragma unroll
        for (int it = 0; it < 3; it++) {
            int idx = it*256 + tid;
            int key = idx / 24, q = idx - key*24;
            float4 v = make_float4(0.f,0.f,0.f,0.f);
            if (k0 + key < kvlen) v = *(const float4*)(Kb + (size_t)(k0+key)*HDIM + q*4);
            unsigned* dst = &Ks[key*FA_SKK + q*4];
            dst[0] = f2tf32(v.x); dst[1] = f2tf32(v.y); dst[2] = f2tf32(v.z); dst[3] = f2tf32(v.w);
        }
        // load V tile transposed: Vs[d][key]
        #pragma unroll
        for (int it = 0; it < 3; it++) {
            int idx = it*256 + tid;
            int key = idx & 31, dq4 = idx >> 5;
            float4 v = make_float4(0.f,0.f,0.f,0.f);
            if (k0 + key < kvlen) v = *(const float4*)(Vb + (size_t)(k0+key)*HDIM + dq4*4);
            Vs[(dq4*4+0)*FA_SP + key] = f2tf32(v.x);
            Vs[(dq4*4+1)*FA_SP + key] = f2tf32(v.y);
            Vs[(dq4*4+2)*FA_SP + key] = f2tf32(v.z);
            Vs[(dq4*4+3)*FA_SP + key] = f2tf32(v.w);
        }
        __syncthreads();

        const bool active = !(causal && k0 > q0 + w*16 + 15);
        if (active) {
            // S = Q K^T (16 x 32)
            float sacc[4][4];
            #pragma unroll
            for (int n = 0; n < 4; n++) { sacc[n][0]=0.f; sacc[n][1]=0.f; sacc[n][2]=0.f; sacc[n][3]=0.f; }
            #pragma unroll
            for (int ks = 0; ks < 12; ks++) {
                unsigned bb[4][2];
                ldsm4(bb[0][0], bb[0][1], bb[1][0], bb[1][1],
                      KsA + (uint32_t)((ks*8 + boffK) * 4));
                ldsm4(bb[2][0], bb[2][1], bb[3][0], bb[3][1],
                      KsA + (uint32_t)((16*FA_SKK + ks*8 + boffK) * 4));
                #pragma unroll
                for (int n = 0; n < 4; n++) mma_tf32(sacc[n], qa[ks], bb[n]);
            }

            // mask
            const bool need_mask = causal || (k0 + 31 >= kvlen);
            if (need_mask) {
                #pragma unroll
                for (int n = 0; n < 4; n++) {
                    int colb = k0 + n*8 + 2*t;
                    #pragma unroll
                    for (int e = 0; e < 4; e++) {
                        int col = colb + (e & 1);
                        int row = (e < 2) ? row0 : row1;
                        if (col >= kvlen || (causal && col > row)) sacc[n][e] = -1e9f;
                    }
                }
            }

            // online softmax update
            float tm0 = fmaxf(fmaxf(sacc[0][0], sacc[0][1]), fmaxf(sacc[1][0], sacc[1][1]));
            tm0 = fmaxf(tm0, fmaxf(fmaxf(sacc[2][0], sacc[2][1]), fmaxf(sacc[3][0], sacc[3][1])));
            float tm1 = fmaxf(fmaxf(sacc[0][2], sacc[0][3]), fmaxf(sacc[1][2], sacc[1][3]));
            tm1 = fmaxf(tm1, fmaxf(fmaxf(sacc[2][2], sacc[2][3]), fmaxf(sacc[3][2], sacc[3][3])));
            tm0 = fmaxf(tm0, __shfl_xor_sync(0xffffffffu, tm0, 1));
            tm0 = fmaxf(tm0, __shfl_xor_sync(0xffffffffu, tm0, 2));
            tm1 = fmaxf(tm1, __shfl_xor_sync(0xffffffffu, tm1, 1));
            tm1 = fmaxf(tm1, __shfl_xor_sync(0xffffffffu, tm1, 2));
            float mn0 = fmaxf(m0, tm0), mn1 = fmaxf(m1, tm1);
            float a0 = __expf(m0 - mn0), a1 = __expf(m1 - mn1);
            float rs0 = 0.f, rs1 = 0.f;
            #pragma unroll
            for (int n = 0; n < 4; n++) {
                sacc[n][0] = __expf(sacc[n][0] - mn0); rs0 += sacc[n][0];
                sacc[n][1] = __expf(sacc[n][1] - mn0); rs0 += sacc[n][1];
                sacc[n][2] = __expf(sacc[n][2] - mn1); rs1 += sacc[n][2];
                sacc[n][3] = __expf(sacc[n][3] - mn1); rs1 += sacc[n][3];
            }
            rs0 += __shfl_xor_sync(0xffffffffu, rs0, 1);
            rs0 += __shfl_xor_sync(0xffffffffu, rs0, 2);
            rs1 += __shfl_xor_sync(0xffffffffu, rs1, 1);
            rs1 += __shfl_xor_sync(0xffffffffu, rs1, 2);
            l0 = l0*a0 + rs0; l1 = l1*a1 + rs1;
            m0 = mn0; m1 = mn1;
            #pragma unroll
            for (int n = 0; n < 12; n++) {
                oacc[n][0] *= a0; oacc[n][1] *= a0;
                oacc[n][2] *= a1; oacc[n][3] *= a1;
            }

            // P -> smem (tf32), per-warp region
            #pragma unroll
            for (int n = 0; n < 4; n++) {
                uint32_t ad0 = PsA + (uint32_t)(((g    )*FA_SP + n*8 + 2*t) * 4);
                uint32_t ad1 = PsA + (uint32_t)(((g + 8)*FA_SP + n*8 + 2*t) * 4);
                unsigned p0 = f2tf32(sacc[n][0]), p1 = f2tf32(sacc[n][1]);
                unsigned p2 = f2tf32(sacc[n][2]), p3 = f2tf32(sacc[n][3]);
                asm volatile("st.shared.v2.b32 [%0], {%1,%2};" :: "r"(ad0), "r"(p0), "r"(p1) : "memory");
                asm volatile("st.shared.v2.b32 [%0], {%1,%2};" :: "r"(ad1), "r"(p2), "r"(p3) : "memory");
            }
            __syncwarp();

            // O += P V
            #pragma unroll
            for (int ks = 0; ks < 4; ks++) {
                unsigned pa[4];
                ldsm4(pa[0], pa[1], pa[2], pa[3], PsA + (uint32_t)((ks*8 + aoffP) * 4));
                unsigned vb[12][2];
                #pragma unroll
                for (int nj = 0; nj < 6; nj++)
                    ldsm4(vb[2*nj][0], vb[2*nj][1], vb[2*nj+1][0], vb[2*nj+1][1],
                          VsA + (uint32_t)((nj*16*FA_SP + ks*8 + boffV) * 4));
                #pragma unroll
                for (int n = 0; n < 12; n++) mma_tf32(oacc[n], pa, vb[n]);
            }
        }
        __syncthreads();
    }

    // normalize + write (unpacked layout)
    float inv0 = 1.f / l0, inv1 = 1.f / l1;
    float* o0 = Oatt + ((size_t)(b*SS + row0))*DD + h*HDIM;
    float* o1 = o0 + (size_t)8*DD;
    #pragma unroll
    for (int n = 0; n < 12; n++) {
        int cc = n*8 + 2*t;
        *(float2*)(o0 + cc) = make_float2(oacc[n][0]*inv0, oacc[n][1]*inv0);
        *(float2*)(o1 + cc) = make_float2(oacc[n][2]*inv1, oacc[n][3]*inv1);
    }
}

// ---------------- elementwise / softmax / LN ----------------
__global__ void add_pe_kernel(const float* __restrict__ te) {
    int idx = blockIdx.x*blockDim.x + threadIdx.x;
    if (idx >= MQ*DD) return;
    int d = idx % DD;
    int s = (idx / DD) % SS;
    int i2 = d & ~1;
    const float kfac = 9.210340371976184f / (float)DD;
    float div = expf(-(float)i2 * kfac);
    float ang = (float)s * div;
    float pe = (d & 1) ? cosf(ang) : sinf(ang);
    g_x[idx] = te[idx] + pe;
}

__global__ __launch_bounds__(256) void add_ln_kernel(const float* __restrict__ y,
                                                     const float* __restrict__ w,
                                                     const float* __restrict__ b) {
    int r = blockIdx.x;
    int t = threadIdx.x;
    float vs[3];
    float s = 0.f;
    #pragma unroll
    for (int i = 0; i < 3; i++) {
        int c = t + i*256;
        vs[i] = g_x[(size_t)r*DD + c] + y[(size_t)r*DD + c];
        s += vs[i];
    }
    float mean = blk_sum256(s) * (1.f/DD);
    float ss = 0.f;
    #pragma unroll
    for (int i = 0; i < 3; i++) { float d0 = vs[i] - mean; ss += d0*d0; }
    float var = blk_sum256(ss) * (1.f/DD);
    float inv = rsqrtf(var + 1e-5f);
    #pragma unroll
    for (int i = 0; i < 3; i++) {
        int c = t + i*256;
        g_x[(size_t)r*DD + c] = (vs[i] - mean)*inv*w[c] + b[c];
    }
}

__global__ __launch_bounds__(256) void softmax_d_kernel(float* __restrict__ out) {
    int r = blockIdx.x;
    int t = threadIdx.x;
    const float* p = g_dec + (size_t)r*DD;
    float vs[3]; float m = -3.0e38f;
    #pragma unroll
    for (int i = 0; i < 3; i++) { vs[i] = p[t + i*256]; m = fmaxf(m, vs[i]); }
    float mx = blk_max256(m);
    float s = 0.f;
    #pragma unroll
    for (int i = 0; i < 3; i++) { vs[i] = expf(vs[i] - mx); s += vs[i]; }
    float sum = blk_sum256(s);
    #pragma unroll
    for (int i = 0; i < 3; i++)
        out[(size_t)r*DD + t + i*256] = vs[i] / sum;
}

__global__ void copy_dec_kernel() {
    int idx = blockIdx.x*blockDim.x + threadIdx.x;
    if (idx >= MDEC*DD) return;
    int c = idx % DD;
    int r = idx / DD;
    int b = r / (SS-1);
    int s = r % (SS-1);
    g_dec[idx] = g_x[((size_t)(b*SS + s))*DD + c];
}

// ---------------- host orchestration ----------------
static inline dim3 gemm_grid(int M, int N) { return dim3((N + 127)/128, (M + 127)/128); }

extern "C" void kernel_launch(void* const* d_in, const int* in_sizes, int n_in,
                              void* d_out, int out_size) {
    (void)in_sizes; (void)n_in; (void)out_size;
    const float* fv          = (const float*)d_in[0];
    const float* te          = (const float*)d_in[1];
    const float* self_in_w   = (const float*)d_in[2];
    const float* self_in_b   = (const float*)d_in[3];
    const float* self_out_w  = (const float*)d_in[4];
    const float* self_out_b  = (const float*)d_in[5];
    const float* cross_in_w  = (const float*)d_in[6];
    const float* cross_in_b  = (const float*)d_in[7];
    const float* cross_out_w = (const float*)d_in[8];
    const float* cross_out_b = (const float*)d_in[9];
    const float* lin1_w      = (const float*)d_in[10];
    const float* lin1_b      = (const float*)d_in[11];
    const float* lin2_w      = (const float*)d_in[12];
    const float* lin2_b      = (const float*)d_in[13];
    const float* ln_w        = (const float*)d_in[14];
    const float* ln_b        = (const float*)d_in[15];
    const float* fc_out_w    = (const float*)d_in[16];
    float* out = (float*)d_out;

    float *x, *qh, *kh, *vh, *att, *y, *ff, *dec;
    cudaGetSymbolAddress((void**)&x,   g_x);
    cudaGetSymbolAddress((void**)&qh,  g_qh);
    cudaGetSymbolAddress((void**)&kh,  g_kh);
    cudaGetSymbolAddress((void**)&vh,  g_vh);
    cudaGetSymbolAddress((void**)&att, g_att);
    cudaGetSymbolAddress((void**)&y,   g_y);
    cudaGetSymbolAddress((void**)&ff,  g_ff);
    cudaGetSymbolAddress((void**)&dec, g_dec);

    add_pe_kernel<<<(MQ*DD + 255)/256, 256>>>(te);

    for (int l = 0; l < NL; l++) {
        const float* siw = self_in_w   + (size_t)l*3*DD*DD;
        const float* sib = self_in_b   + (size_t)l*3*DD;
        const float* sow = self_out_w  + (size_t)l*DD*DD;
        const float* sob = self_out_b  + (size_t)l*DD;
        const float* ciw = cross_in_w  + (size_t)l*3*DD*DD;
        const float* cib = cross_in_b  + (size_t)l*3*DD;
        const float* cow = cross_out_w + (size_t)l*DD*DD;
        const float* cob = cross_out_b + (size_t)l*DD;
        const float* l1w = lin1_w + (size_t)l*FFD*DD;
        const float* l1b = lin1_b + (size_t)l*FFD;
        const float* l2w = lin2_w + (size_t)l*DD*FFD;
        const float* l2b = lin2_b + (size_t)l*DD;

        // ---- self attention ----
        gemm_nt_tf32<<<gemm_grid(MQ, 3*DD), 256>>>(x, siw, sib, nullptr, MQ, 3*DD, DD, 0, 1, qh, kh, vh);
        flash_attn<<<dim3(SS/128, BHH), 256>>>(qh, kh, vh, att, SS, 1);
        gemm_nt_tf32<<<gemm_grid(MQ, DD), 256>>>(att, sow, sob, y, MQ, DD, DD, 0, 0, nullptr, nullptr, nullptr);
        add_ln_kernel<<<MQ, 256>>>(y, ln_w + (size_t)(l*3 + 0)*DD, ln_b + (size_t)(l*3 + 0)*DD);

        // ---- cross attention ----
        gemm_nt_tf32<<<gemm_grid(MQ, DD), 256>>>(x, ciw, cib, nullptr, MQ, DD, DD, 0, 2, qh, nullptr, nullptr);
        gemm_nt_tf32<<<gemm_grid(MKV, 2*DD), 256>>>(fv, ciw + (size_t)DD*DD, cib + DD, nullptr,
                                                    MKV, 2*DD, DD, 0, 3, nullptr, kh, vh);
        flash_attn<<<dim3(SS/128, BHH), 256>>>(qh, kh, vh, att, NVV, 0);
        gemm_nt_tf32<<<gemm_grid(MQ, DD), 256>>>(att, cow, cob, y, MQ, DD, DD, 0, 0, nullptr, nullptr, nullptr);
        add_ln_kernel<<<MQ, 256>>>(y, ln_w + (size_t)(l*3 + 1)*DD, ln_b + (size_t)(l*3 + 1)*DD);

        // ---- FFN ----
        gemm_nt_tf32<<<gemm_grid(MQ, FFD), 256>>>(x, l1w, l1b, ff, MQ, FFD, DD, 1, 0, nullptr, nullptr, nullptr);
        gemm_nt_tf32<<<gemm_grid(MQ, DD), 256>>>(ff, l2w, l2b, y, MQ, DD, FFD, 0, 0, nullptr, nullptr, nullptr);
        add_ln_kernel<<<MQ, 256>>>(y, ln_w + (size_t)(l*3 + 2)*DD, ln_b + (size_t)(l*3 + 2)*DD);
    }

    // ---- outputs: logits then F_t ----
    copy_dec_kernel<<<(MDEC*DD + 255)/256, 256>>>();
    gemm_nt_tf32<<<gemm_grid(MDEC, VOC), 256>>>(dec, fc_out_w, nullptr, out, MDEC, VOC, DD, 0, 0, nullptr, nullptr, nullptr);
    softmax_d_kernel<<<MDEC, 256>>>(out + (size_t)MDEC*VOC);
}

// round 8
// speedup vs baseline: 3.7640x; 1.0640x over previous
#include <cuda_runtime.h>
#include <math.h>
#include <stdint.h>

// ---------------- problem constants ----------------
#define BB   16
#define SS   256
#define NVV  196
#define DD   768
#define FFD  2048
#define VOC  30522
#define NL   6
#define NHH  8
#define HDIM 96
#define MQ   (BB*SS)          // 4096 query rows
#define MKV  (BB*NVV)         // 3136 memory rows
#define BHH  (BB*NHH)         // 128 batch*heads
#define MDEC (BB*(SS-1))      // 4080 decoded rows

// ---------------- scratch (static device memory; no allocations) ----------------
__device__ float g_x  [MQ*DD];          // exact residual stream
__device__ float g_xr [MQ*DD];          // tf32-rounded copy (GEMM input)
__device__ float g_qh [BHH*SS*HDIM];
__device__ float g_kh [BHH*SS*HDIM];
__device__ float g_vh [BHH*SS*HDIM];
__device__ float g_att[MQ*DD];          // rounded at producer (flash)
__device__ float g_y  [MQ*DD];
__device__ float g_ff [MQ*FFD];         // rounded at producer (relu epilogue)
__device__ float g_dec [MDEC*DD];       // exact (softmax input)
__device__ float g_decr[MDEC*DD];       // rounded (GEMM input)
__device__ float g_fvr[MKV*DD];         // rounded fv

// pre-rounded weights
__device__ float g_w_selfin [NL*3*DD*DD];
__device__ float g_w_selfout[NL*DD*DD];
__device__ float g_w_crossin[NL*3*DD*DD];
__device__ float g_w_crossout[NL*DD*DD];
__device__ float g_w_lin1   [NL*FFD*DD];
__device__ float g_w_lin2   [NL*DD*FFD];
__device__ float g_w_fc     [VOC*DD];

// ---------------- reductions (256-thread blocks) ----------------
__device__ __forceinline__ float blk_sum256(float v) {
    __shared__ float sh[8];
    #pragma unroll
    for (int o = 16; o > 0; o >>= 1) v += __shfl_xor_sync(0xffffffffu, v, o);
    __syncthreads();
    if ((threadIdx.x & 31) == 0) sh[threadIdx.x >> 5] = v;
    __syncthreads();
    float r = sh[0];
    #pragma unroll
    for (int i = 1; i < 8; i++) r += sh[i];
    return r;
}

__device__ __forceinline__ float blk_max256(float v) {
    __shared__ float sh[8];
    #pragma unroll
    for (int o = 16; o > 0; o >>= 1) v = fmaxf(v, __shfl_xor_sync(0xffffffffu, v, o));
    __syncthreads();
    if ((threadIdx.x & 31) == 0) sh[threadIdx.x >> 5] = v;
    __syncthreads();
    float r = sh[0];
    #pragma unroll
    for (int i = 1; i < 8; i++) r = fmaxf(r, sh[i]);
    return r;
}

// ---------------- tf32 / mma helpers ----------------
__device__ __forceinline__ unsigned f2tf32(float f) {
    unsigned u;
    asm("cvt.rna.tf32.f32 %0, %1;" : "=r"(u) : "f"(f));
    return u;
}
__device__ __forceinline__ float rnd_tf32(float f) { return __uint_as_float(f2tf32(f)); }

__device__ __forceinline__ void mma_tf32(float (&d)[4], const unsigned (&a)[4], const unsigned (&b)[2]) {
    asm volatile(
        "mma.sync.aligned.m16n8k8.row.col.f32.tf32.tf32.f32 "
        "{%0,%1,%2,%3}, {%4,%5,%6,%7}, {%8,%9}, {%0,%1,%2,%3};\n"
        : "+f"(d[0]), "+f"(d[1]), "+f"(d[2]), "+f"(d[3])
        : "r"(a[0]), "r"(a[1]), "r"(a[2]), "r"(a[3]), "r"(b[0]), "r"(b[1]));
}

__device__ __forceinline__ void ldsm4(unsigned &d0, unsigned &d1, unsigned &d2, unsigned &d3, uint32_t a) {
    asm volatile("ldmatrix.sync.aligned.m8n8.x4.shared.b16 {%0,%1,%2,%3}, [%4];"
                 : "=r"(d0), "=r"(d1), "=r"(d2), "=r"(d3) : "r"(a));
}

__device__ __forceinline__ uint32_t smem_u32(const void* p) {
    uint32_t a;
    asm("{ .reg .u64 t; cvta.to.shared.u64 t, %1; cvt.u32.u64 %0, t; }" : "=r"(a) : "l"(p));
    return a;
}

__device__ __forceinline__ void cp16(uint32_t dst, const void* src, bool pred) {
    int sz = pred ? 16 : 0;
    asm volatile("cp.async.cg.shared.global [%0], [%1], 16, %2;" :: "r"(dst), "l"(src), "r"(sz));
}
#define CP_COMMIT() asm volatile("cp.async.commit_group;" ::: "memory")
#define CP_WAIT1()  asm volatile("cp.async.wait_group 1;" ::: "memory")

// ---------------- round-to-tf32 pass (float4) ----------------
__global__ void round_tf32_kernel(const float4* __restrict__ in, float4* __restrict__ out, int n4) {
    int i = blockIdx.x*blockDim.x + threadIdx.x;
    int stride = gridDim.x*blockDim.x;
    for (; i < n4; i += stride) {
        float4 v = in[i];
        v.x = rnd_tf32(v.x); v.y = rnd_tf32(v.y); v.z = rnd_tf32(v.z); v.w = rnd_tf32(v.w);
        out[i] = v;
    }
}

// ---------------- main dense GEMM (tf32 mma, cp.async 3-stage, no in-loop cvt) ----------------
// Inputs A,B must be pre-rounded to tf32 bit patterns.  K % 16 == 0, K/16 >= 2.
// mode 0: row-major C (+relu)(+round). 1: QKV pack. 2: Q pack. 3: KV pack.
#define SK 20
#define STGW (2*128*SK)            // words per stage (A+B)
#define GEMM_DSMEM (3*STGW*4)      // 61440 bytes

__global__ __launch_bounds__(256, 2) void gemm_nt_tf32(
    const float* __restrict__ A, const float* __restrict__ Bm,
    const float* __restrict__ bias, float* __restrict__ C,
    int M, int N, int K, int relu, int rnd, int mode,
    float* __restrict__ dq, float* __restrict__ dk, float* __restrict__ dv)
{
    extern __shared__ unsigned sm[];
    const uint32_t sb = smem_u32(sm);
    const int tid  = threadIdx.x;
    const int lane = tid & 31;
    const int wid  = tid >> 5;
    const int m0   = blockIdx.y * 128;
    const int n0   = blockIdx.x * 128;
    const int wm   = (wid & 3) * 32;
    const int wn   = (wid >> 2) * 64;
    const int g    = lane >> 2;
    const int t    = lane & 3;

    const int aoff = ((lane & 7) + ((lane >> 3) & 1) * 8) * SK + ((lane >> 4) & 1) * 4;
    const int boff = ((lane & 7) + ((lane >> 4) & 1) * 8) * SK + ((lane >> 3) & 1) * 4;

    const int lrow = tid >> 2;           // 0..63
    const int lq   = (tid & 3) * 4;      // word offset 0,4,8,12

    float acc[2][8][4];
    #pragma unroll
    for (int mi = 0; mi < 2; mi++)
        #pragma unroll
        for (int ni = 0; ni < 8; ni++)
            #pragma unroll
            for (int e = 0; e < 4; e++) acc[mi][ni][e] = 0.f;

    const int NC = K >> 4;

    // prologue: issue chunks 0 and 1
    #pragma unroll
    for (int pc = 0; pc < 2; pc++) {
        const int k0 = pc << 4;
        const uint32_t sA = sb + (uint32_t)(pc * STGW * 4);
        const uint32_t sB = sA + (uint32_t)(128*SK*4);
        #pragma unroll
        for (int it = 0; it < 2; it++) {
            int row = lrow + it*64;
            int gm = m0 + row;
            cp16(sA + (uint32_t)((row*SK + lq)*4),
                 A + (size_t)(gm < M ? gm : 0)*K + k0 + lq, gm < M);
            int gn = n0 + row;
            cp16(sB + (uint32_t)((row*SK + lq)*4),
                 Bm + (size_t)(gn < N ? gn : 0)*K + k0 + lq, gn < N);
        }
        CP_COMMIT();
    }

    for (int c = 0; c < NC; c++) {
        CP_WAIT1();
        __syncthreads();

        // issue chunk c+2 into stage (c+2)%3
        if (c + 2 < NC) {
            const int k0 = (c + 2) << 4;
            const int s = (c + 2) % 3;
            const uint32_t sA = sb + (uint32_t)(s * STGW * 4);
            const uint32_t sB = sA + (uint32_t)(128*SK*4);
            #pragma unroll
            for (int it = 0; it < 2; it++) {
                int row = lrow + it*64;
                int gm = m0 + row;
                cp16(sA + (uint32_t)((row*SK + lq)*4),
                     A + (size_t)(gm < M ? gm : 0)*K + k0 + lq, gm < M);
                int gn = n0 + row;
                cp16(sB + (uint32_t)((row*SK + lq)*4),
                     Bm + (size_t)(gn < N ? gn : 0)*K + k0 + lq, gn < N);
            }
        }
        CP_COMMIT();

        // compute stage c%3
        const int s = c % 3;
        const uint32_t Acur = sb + (uint32_t)(s * STGW * 4);
        const uint32_t Bcur = Acur + (uint32_t)(128*SK*4);
        #pragma unroll
        for (int ks = 0; ks < 16; ks += 8) {
            unsigned a[2][4], b[8][2];
            #pragma unroll
            for (int mi = 0; mi < 2; mi++)
                ldsm4(a[mi][0], a[mi][1], a[mi][2], a[mi][3],
                      Acur + (uint32_t)(((wm + mi*16)*SK + ks + aoff) * 4));
            #pragma unroll
            for (int nj = 0; nj < 4; nj++)
                ldsm4(b[2*nj][0], b[2*nj][1], b[2*nj+1][0], b[2*nj+1][1],
                      Bcur + (uint32_t)(((wn + nj*16)*SK + ks + boff) * 4));
            #pragma unroll
            for (int mi = 0; mi < 2; mi++)
                #pragma unroll
                for (int ni = 0; ni < 8; ni++)
                    mma_tf32(acc[mi][ni], a[mi], b[ni]);
        }
    }

    // ---- epilogue ----
    #pragma unroll
    for (int mi = 0; mi < 2; mi++) {
        #pragma unroll
        for (int half = 0; half < 2; half++) {
            int r = m0 + wm + mi*16 + g + half*8;
            if (r >= M) continue;
            #pragma unroll
            for (int ni = 0; ni < 8; ni++) {
                int cn = n0 + wn + ni*8 + 2*t;
                if (cn >= N) continue;
                float v0 = acc[mi][ni][half*2 + 0];
                float v1 = acc[mi][ni][half*2 + 1];
                if (bias) { v0 += bias[cn]; if (cn+1 < N) v1 += bias[cn+1]; }
                if (mode == 0) {
                    if (relu) { v0 = fmaxf(v0, 0.f); v1 = fmaxf(v1, 0.f); }
                    if (rnd)  { v0 = rnd_tf32(v0); v1 = rnd_tf32(v1); }
                    if (cn + 1 < N) *(float2*)(C + (size_t)r*N + cn) = make_float2(v0, v1);
                    else            C[(size_t)r*N + cn] = v0;
                } else {
                    int bb_, s_, which, rem, hh, dd;
                    float* base;
                    if (mode == 1) {         // self QKV, rows b*256+s
                        bb_ = r >> 8; s_ = r & 255;
                        which = cn / DD; rem = cn - which*DD;
                        hh = rem / HDIM; dd = rem - hh*HDIM;
                        base = (which == 0) ? dq : (which == 1) ? dk : dv;
                        base += (((size_t)((bb_<<3) + hh))*SS + s_)*HDIM + dd;
                    } else if (mode == 2) {  // cross Q
                        bb_ = r >> 8; s_ = r & 255;
                        hh = cn / HDIM; dd = cn - hh*HDIM;
                        base = dq + (((size_t)((bb_<<3) + hh))*SS + s_)*HDIM + dd;
                    } else {                 // cross KV, rows b*196+s
                        bb_ = r / NVV; s_ = r - bb_*NVV;
                        which = cn / DD; rem = cn - which*DD;
                        hh = rem / HDIM; dd = rem - hh*HDIM;
                        base = ((which == 0) ? dk : dv);
                        base += (((size_t)((bb_<<3) + hh))*NVV + s_)*HDIM + dd;
                    }
                    *(float2*)base = make_float2(v0, v1);
                }
            }
        }
    }
}

// ---------------- fused flash attention (tf32 mma) ----------------
#define FA_SP  36
#define FA_SKK 100

__global__ __launch_bounds__(256) void flash_attn(
    const float* __restrict__ Qh, const float* __restrict__ Kh, const float* __restrict__ Vh,
    float* __restrict__ Oatt, int kvlen, int causal)
{
    __shared__ unsigned Ks[32*FA_SKK];
    __shared__ unsigned Vs[96*FA_SP];
    __shared__ unsigned Ps[8][16*FA_SP];
    const int tid = threadIdx.x, w = tid >> 5, lane = tid & 31;
    const int g = lane >> 2, t = lane & 3;
    const int z = blockIdx.y;
    const int b = z >> 3, h = z & 7;
    const int q0 = blockIdx.x * 128;
    const float scale = 0.1020620726159658f;   // 1/sqrt(96)

    const float* Qb = Qh + ((size_t)z*SS + q0)*HDIM;
    const float* Kb = Kh + (size_t)z*kvlen*HDIM;
    const float* Vb = Vh + (size_t)z*kvlen*HDIM;

    unsigned qa[12][4];
    {
        const float* qr0 = Qb + (w*16 + g)*HDIM;
        const float* qr1 = qr0 + 8*HDIM;
        #pragma unroll
        for (int ks = 0; ks < 12; ks++) {
            qa[ks][0] = f2tf32(qr0[ks*8 + t] * scale);
            qa[ks][1] = f2tf32(qr1[ks*8 + t] * scale);
            qa[ks][2] = f2tf32(qr0[ks*8 + t + 4] * scale);
            qa[ks][3] = f2tf32(qr1[ks*8 + t + 4] * scale);
        }
    }

    float oacc[12][4];
    #pragma unroll
    for (int n = 0; n < 12; n++) { oacc[n][0]=0.f; oacc[n][1]=0.f; oacc[n][2]=0.f; oacc[n][3]=0.f; }
    float m0 = -1e30f, m1 = -1e30f, l0 = 0.f, l1 = 0.f;
    const int row0 = q0 + w*16 + g;
    const int row1 = row0 + 8;

    const uint32_t KsA = smem_u32(Ks);
    const uint32_t VsA = smem_u32(Vs);
    const uint32_t PsA = smem_u32(Ps[w]);
    const int boffK = ((lane & 7) + ((lane >> 4) & 1)*8)*FA_SKK + ((lane >> 3) & 1)*4;
    const int boffV = ((lane & 7) + ((lane >> 4) & 1)*8)*FA_SP  + ((lane >> 3) & 1)*4;
    const int aoffP = ((lane & 7) + ((lane >> 3) & 1)*8)*FA_SP  + ((lane >> 4) & 1)*4;

    int ntiles = (kvlen + 31) >> 5;
    if (causal) { int lim = ((q0 + 127) >> 5) + 1; if (lim < ntiles) ntiles = lim; }

    for (int j = 0; j < ntiles; j++) {
        const int k0 = j*32;

        #pragma unroll
        for (int it = 0; it < 3; it++) {
            int idx = it*256 + tid;
            int key = idx / 24, q = idx - key*24;
            float4 v = make_float4(0.f,0.f,0.f,0.f);
            if (k0 + key < kvlen) v = *(const float4*)(Kb + (size_t)(k0+key)*HDIM + q*4);
            unsigned* dst = &Ks[key*FA_SKK + q*4];
            dst[0] = f2tf32(v.x); dst[1] = f2tf32(v.y); dst[2] = f2tf32(v.z); dst[3] = f2tf32(v.w);
        }
        #pragma unroll
        for (int it = 0; it < 3; it++) {
            int idx = it*256 + tid;
            int key = idx & 31, dq4 = idx >> 5;
            float4 v = make_float4(0.f,0.f,0.f,0.f);
            if (k0 + key < kvlen) v = *(const float4*)(Vb + (size_t)(k0+key)*HDIM + dq4*4);
            Vs[(dq4*4+0)*FA_SP + key] = f2tf32(v.x);
            Vs[(dq4*4+1)*FA_SP + key] = f2tf32(v.y);
            Vs[(dq4*4+2)*FA_SP + key] = f2tf32(v.z);
            Vs[(dq4*4+3)*FA_SP + key] = f2tf32(v.w);
        }
        __syncthreads();

        const bool active = !(causal && k0 > q0 + w*16 + 15);
        if (active) {
            float sacc[4][4];
            #pragma unroll
            for (int n = 0; n < 4; n++) { sacc[n][0]=0.f; sacc[n][1]=0.f; sacc[n][2]=0.f; sacc[n][3]=0.f; }
            #pragma unroll
            for (int ks = 0; ks < 12; ks++) {
                unsigned bb[4][2];
                ldsm4(bb[0][0], bb[0][1], bb[1][0], bb[1][1],
                      KsA + (uint32_t)((ks*8 + boffK) * 4));
                ldsm4(bb[2][0], bb[2][1], bb[3][0], bb[3][1],
                      KsA + (uint32_t)((16*FA_SKK + ks*8 + boffK) * 4));
                #pragma unroll
                for (int n = 0; n < 4; n++) mma_tf32(sacc[n], qa[ks], bb[n]);
            }

            const bool need_mask = causal || (k0 + 31 >= kvlen);
            if (need_mask) {
                #pragma unroll
                for (int n = 0; n < 4; n++) {
                    int colb = k0 + n*8 + 2*t;
                    #pragma unroll
                    for (int e = 0; e < 4; e++) {
                        int col = colb + (e & 1);
                        int row = (e < 2) ? row0 : row1;
                        if (col >= kvlen || (causal && col > row)) sacc[n][e] = -1e9f;
                    }
                }
            }

            float tm0 = fmaxf(fmaxf(sacc[0][0], sacc[0][1]), fmaxf(sacc[1][0], sacc[1][1]));
            tm0 = fmaxf(tm0, fmaxf(fmaxf(sacc[2][0], sacc[2][1]), fmaxf(sacc[3][0], sacc[3][1])));
            float tm1 = fmaxf(fmaxf(sacc[0][2], sacc[0][3]), fmaxf(sacc[1][2], sacc[1][3]));
            tm1 = fmaxf(tm1, fmaxf(fmaxf(sacc[2][2], sacc[2][3]), fmaxf(sacc[3][2], sacc[3][3])));
            tm0 = fmaxf(tm0, __shfl_xor_sync(0xffffffffu, tm0, 1));
            tm0 = fmaxf(tm0, __shfl_xor_sync(0xffffffffu, tm0, 2));
            tm1 = fmaxf(tm1, __shfl_xor_sync(0xffffffffu, tm1, 1));
            tm1 = fmaxf(tm1, __shfl_xor_sync(0xffffffffu, tm1, 2));
            float mn0 = fmaxf(m0, tm0), mn1 = fmaxf(m1, tm1);
            float a0 = __expf(m0 - mn0), a1 = __expf(m1 - mn1);
            float rs0 = 0.f, rs1 = 0.f;
            #pragma unroll
            for (int n = 0; n < 4; n++) {
                sacc[n][0] = __expf(sacc[n][0] - mn0); rs0 += sacc[n][0];
                sacc[n][1] = __expf(sacc[n][1] - mn0); rs0 += sacc[n][1];
                sacc[n][2] = __expf(sacc[n][2] - mn1); rs1 += sacc[n][2];
                sacc[n][3] = __expf(sacc[n][3] - mn1); rs1 += sacc[n][3];
            }
            rs0 += __shfl_xor_sync(0xffffffffu, rs0, 1);
            rs0 += __shfl_xor_sync(0xffffffffu, rs0, 2);
            rs1 += __shfl_xor_sync(0xffffffffu, rs1, 1);
            rs1 += __shfl_xor_sync(0xffffffffu, rs1, 2);
            l0 = l0*a0 + rs0; l1 = l1*a1 + rs1;
            m0 = mn0; m1 = mn1;
            #pragma unroll
            for (int n = 0; n < 12; n++) {
                oacc[n][0] *= a0; oacc[n][1] *= a0;
                oacc[n][2] *= a1; oacc[n][3] *= a1;
            }

            #pragma unroll
            for (int n = 0; n < 4; n++) {
                uint32_t ad0 = PsA + (uint32_t)(((g    )*FA_SP + n*8 + 2*t) * 4);
                uint32_t ad1 = PsA + (uint32_t)(((g + 8)*FA_SP + n*8 + 2*t) * 4);
                unsigned p0 = f2tf32(sacc[n][0]), p1 = f2tf32(sacc[n][1]);
                unsigned p2 = f2tf32(sacc[n][2]), p3 = f2tf32(sacc[n][3]);
                asm volatile("st.shared.v2.b32 [%0], {%1,%2};" :: "r"(ad0), "r"(p0), "r"(p1) : "memory");
                asm volatile("st.shared.v2.b32 [%0], {%1,%2};" :: "r"(ad1), "r"(p2), "r"(p3) : "memory");
            }
            __syncwarp();

            #pragma unroll
            for (int ks = 0; ks < 4; ks++) {
                unsigned pa[4];
                ldsm4(pa[0], pa[1], pa[2], pa[3], PsA + (uint32_t)((ks*8 + aoffP) * 4));
                unsigned vb[12][2];
                #pragma unroll
                for (int nj = 0; nj < 6; nj++)
                    ldsm4(vb[2*nj][0], vb[2*nj][1], vb[2*nj+1][0], vb[2*nj+1][1],
                          VsA + (uint32_t)((nj*16*FA_SP + ks*8 + boffV) * 4));
                #pragma unroll
                for (int n = 0; n < 12; n++) mma_tf32(oacc[n], pa, vb[n]);
            }
        }
        __syncthreads();
    }

    // normalize + write (unpacked layout), rounded to tf32 for the next GEMM
    float inv0 = 1.f / l0, inv1 = 1.f / l1;
    float* o0 = Oatt + ((size_t)(b*SS + row0))*DD + h*HDIM;
    float* o1 = o0 + (size_t)8*DD;
    #pragma unroll
    for (int n = 0; n < 12; n++) {
        int cc = n*8 + 2*t;
        *(float2*)(o0 + cc) = make_float2(rnd_tf32(oacc[n][0]*inv0), rnd_tf32(oacc[n][1]*inv0));
        *(float2*)(o1 + cc) = make_float2(rnd_tf32(oacc[n][2]*inv1), rnd_tf32(oacc[n][3]*inv1));
    }
}

// ---------------- elementwise / softmax / LN ----------------
__global__ void add_pe_kernel(const float* __restrict__ te) {
    int idx = blockIdx.x*blockDim.x + threadIdx.x;
    if (idx >= MQ*DD) return;
    int d = idx % DD;
    int s = (idx / DD) % SS;
    int i2 = d & ~1;
    const float kfac = 9.210340371976184f / (float)DD;
    float div = expf(-(float)i2 * kfac);
    float ang = (float)s * div;
    float pe = (d & 1) ? cosf(ang) : sinf(ang);
    float v = te[idx] + pe;
    g_x[idx] = v;
    g_xr[idx] = rnd_tf32(v);
}

__global__ __launch_bounds__(256) void add_ln_kernel(const float* __restrict__ y,
                                                     const float* __restrict__ w,
                                                     const float* __restrict__ b) {
    int r = blockIdx.x;
    int t = threadIdx.x;
    float vs[3];
    float s = 0.f;
    #pragma unroll
    for (int i = 0; i < 3; i++) {
        int c = t + i*256;
        vs[i] = g_x[(size_t)r*DD + c] + y[(size_t)r*DD + c];
        s += vs[i];
    }
    float mean = blk_sum256(s) * (1.f/DD);
    float ss = 0.f;
    #pragma unroll
    for (int i = 0; i < 3; i++) { float d0 = vs[i] - mean; ss += d0*d0; }
    float var = blk_sum256(ss) * (1.f/DD);
    float inv = rsqrtf(var + 1e-5f);
    #pragma unroll
    for (int i = 0; i < 3; i++) {
        int c = t + i*256;
        float o = (vs[i] - mean)*inv*w[c] + b[c];
        g_x[(size_t)r*DD + c] = o;
        g_xr[(size_t)r*DD + c] = rnd_tf32(o);
    }
}

__global__ __launch_bounds__(256) void softmax_d_kernel(float* __restrict__ out) {
    int r = blockIdx.x;
    int t = threadIdx.x;
    const float* p = g_dec + (size_t)r*DD;
    float vs[3]; float m = -3.0e38f;
    #pragma unroll
    for (int i = 0; i < 3; i++) { vs[i] = p[t + i*256]; m = fmaxf(m, vs[i]); }
    float mx = blk_max256(m);
    float s = 0.f;
    #pragma unroll
    for (int i = 0; i < 3; i++) { vs[i] = expf(vs[i] - mx); s += vs[i]; }
    float sum = blk_sum256(s);
    #pragma unroll
    for (int i = 0; i < 3; i++)
        out[(size_t)r*DD + t + i*256] = vs[i] / sum;
}

__global__ void copy_dec_kernel() {
    int idx = blockIdx.x*blockDim.x + threadIdx.x;
    if (idx >= MDEC*DD) return;
    int c = idx % DD;
    int r = idx / DD;
    int b = r / (SS-1);
    int s = r % (SS-1);
    float v = g_x[((size_t)(b*SS + s))*DD + c];
    g_dec[idx] = v;
    g_decr[idx] = rnd_tf32(v);
}

// ---------------- host orchestration ----------------
static inline dim3 gemm_grid(int M, int N) { return dim3((N + 127)/128, (M + 127)/128); }

static void round_arr(const float* src, float* dst, size_t n) {
    int n4 = (int)(n >> 2);
    int blocks = (n4 + 255)/256;
    if (blocks > 8192) blocks = 8192;
    round_tf32_kernel<<<blocks, 256>>>((const float4*)src, (float4*)dst, n4);
}

extern "C" void kernel_launch(void* const* d_in, const int* in_sizes, int n_in,
                              void* d_out, int out_size) {
    (void)in_sizes; (void)n_in; (void)out_size;
    const float* fv          = (const float*)d_in[0];
    const float* te          = (const float*)d_in[1];
    const float* self_in_w   = (const float*)d_in[2];
    const float* self_in_b   = (const float*)d_in[3];
    const float* self_out_w  = (const float*)d_in[4];
    const float* self_out_b  = (const float*)d_in[5];
    const float* cross_in_w  = (const float*)d_in[6];
    const float* cross_in_b  = (const float*)d_in[7];
    const float* cross_out_w = (const float*)d_in[8];
    const float* cross_out_b = (const float*)d_in[9];
    const float* lin1_w      = (const float*)d_in[10];
    const float* lin1_b      = (const float*)d_in[11];
    const float* lin2_w      = (const float*)d_in[12];
    const float* lin2_b      = (const float*)d_in[13];
    const float* ln_w        = (const float*)d_in[14];
    const float* ln_b        = (const float*)d_in[15];
    const float* fc_out_w    = (const float*)d_in[16];
    float* out = (float*)d_out;

    cudaFuncSetAttribute(gemm_nt_tf32, cudaFuncAttributeMaxDynamicSharedMemorySize, GEMM_DSMEM);

    float *x, *xr, *qh, *kh, *vh, *att, *y, *ff, *dec, *decr, *fvr;
    float *wsi, *wso, *wci, *wco, *wl1, *wl2, *wfc;
    cudaGetSymbolAddress((void**)&x,    g_x);
    cudaGetSymbolAddress((void**)&xr,   g_xr);
    cudaGetSymbolAddress((void**)&qh,   g_qh);
    cudaGetSymbolAddress((void**)&kh,   g_kh);
    cudaGetSymbolAddress((void**)&vh,   g_vh);
    cudaGetSymbolAddress((void**)&att,  g_att);
    cudaGetSymbolAddress((void**)&y,    g_y);
    cudaGetSymbolAddress((void**)&ff,   g_ff);
    cudaGetSymbolAddress((void**)&dec,  g_dec);
    cudaGetSymbolAddress((void**)&decr, g_decr);
    cudaGetSymbolAddress((void**)&fvr,  g_fvr);
    cudaGetSymbolAddress((void**)&wsi,  g_w_selfin);
    cudaGetSymbolAddress((void**)&wso,  g_w_selfout);
    cudaGetSymbolAddress((void**)&wci,  g_w_crossin);
    cudaGetSymbolAddress((void**)&wco,  g_w_crossout);
    cudaGetSymbolAddress((void**)&wl1,  g_w_lin1);
    cudaGetSymbolAddress((void**)&wl2,  g_w_lin2);
    cudaGetSymbolAddress((void**)&wfc,  g_w_fc);

    // pre-round all weights + fv to tf32 bit patterns
    round_arr(self_in_w,   wsi, (size_t)NL*3*DD*DD);
    round_arr(self_out_w,  wso, (size_t)NL*DD*DD);
    round_arr(cross_in_w,  wci, (size_t)NL*3*DD*DD);
    round_arr(cross_out_w, wco, (size_t)NL*DD*DD);
    round_arr(lin1_w,      wl1, (size_t)NL*FFD*DD);
    round_arr(lin2_w,      wl2, (size_t)NL*DD*FFD);
    round_arr(fc_out_w,    wfc, (size_t)VOC*DD);
    round_arr(fv,          fvr, (size_t)MKV*DD);

    add_pe_kernel<<<(MQ*DD + 255)/256, 256>>>(te);

    for (int l = 0; l < NL; l++) {
        const float* siw = wsi + (size_t)l*3*DD*DD;
        const float* sib = self_in_b   + (size_t)l*3*DD;
        const float* sow = wso + (size_t)l*DD*DD;
        const float* sob = self_out_b  + (size_t)l*DD;
        const float* ciw = wci + (size_t)l*3*DD*DD;
        const float* cib = cross_in_b  + (size_t)l*3*DD;
        const float* cow = wco + (size_t)l*DD*DD;
        const float* cob = cross_out_b + (size_t)l*DD;
        const float* l1w = wl1 + (size_t)l*FFD*DD;
        const float* l1b = lin1_b + (size_t)l*FFD;
        const float* l2w = wl2 + (size_t)l*DD*FFD;
        const float* l2b = lin2_b + (size_t)l*DD;

        // ---- self attention ----
        gemm_nt_tf32<<<gemm_grid(MQ, 3*DD), 256, GEMM_DSMEM>>>(xr, siw, sib, nullptr, MQ, 3*DD, DD, 0, 0, 1, qh, kh, vh);
        flash_attn<<<dim3(SS/128, BHH), 256>>>(qh, kh, vh, att, SS, 1);
        gemm_nt_tf32<<<gemm_grid(MQ, DD), 256, GEMM_DSMEM>>>(att, sow, sob, y, MQ, DD, DD, 0, 0, 0, nullptr, nullptr, nullptr);
        add_ln_kernel<<<MQ, 256>>>(y, ln_w + (size_t)(l*3 + 0)*DD, ln_b + (size_t)(l*3 + 0)*DD);

        // ---- cross attention ----
        gemm_nt_tf32<<<gemm_grid(MQ, DD), 256, GEMM_DSMEM>>>(xr, ciw, cib, nullptr, MQ, DD, DD, 0, 0, 2, qh, nullptr, nullptr);
        gemm_nt_tf32<<<gemm_grid(MKV, 2*DD), 256, GEMM_DSMEM>>>(fvr, ciw + (size_t)DD*DD, cib + DD, nullptr,
                                                                MKV, 2*DD, DD, 0, 0, 3, nullptr, kh, vh);
        flash_attn<<<dim3(SS/128, BHH), 256>>>(qh, kh, vh, att, NVV, 0);
        gemm_nt_tf32<<<gemm_grid(MQ, DD), 256, GEMM_DSMEM>>>(att, cow, cob, y, MQ, DD, DD, 0, 0, 0, nullptr, nullptr, nullptr);
        add_ln_kernel<<<MQ, 256>>>(y, ln_w + (size_t)(l*3 + 1)*DD, ln_b + (size_t)(l*3 + 1)*DD);

        // ---- FFN ----
        gemm_nt_tf32<<<gemm_grid(MQ, FFD), 256, GEMM_DSMEM>>>(xr, l1w, l1b, ff, MQ, FFD, DD, 1, 1, 0, nullptr, nullptr, nullptr);
        gemm_nt_tf32<<<gemm_grid(MQ, DD), 256, GEMM_DSMEM>>>(ff, l2w, l2b, y, MQ, DD, FFD, 0, 0, 0, nullptr, nullptr, nullptr);
        add_ln_kernel<<<MQ, 256>>>(y, ln_w + (size_t)(l*3 + 2)*DD, ln_b + (size_t)(l*3 + 2)*DD);
    }

    // ---- outputs: logits then F_t ----
    copy_dec_kernel<<<(MDEC*DD + 255)/256, 256>>>();
    gemm_nt_tf32<<<gemm_grid(MDEC, VOC), 256, GEMM_DSMEM>>>(decr, wfc, nullptr, out, MDEC, VOC, DD, 0, 0, 0, nullptr, nullptr, nullptr);
    softmax_d_kernel<<<MDEC, 256>>>(out + (size_t)MDEC*VOC);
}

// round 9
// speedup vs baseline: 5.6378x; 1.4978x over previous
#include <cuda_runtime.h>
#include <cuda_fp16.h>
#include <math.h>
#include <stdint.h>

// ---------------- problem constants ----------------
#define BB   16
#define SS   256
#define NVV  196
#define DD   768
#define FFD  2048
#define VOC  30522
#define NL   6
#define NHH  8
#define HDIM 96
#define MQ   (BB*SS)          // 4096
#define MKV  (BB*NVV)         // 3136
#define BHH  (BB*NHH)         // 128
#define MDEC (BB*(SS-1))      // 4080

// ---------------- scratch (static device memory; no allocations) ----------------
__device__ float  g_x  [MQ*DD];         // exact residual stream
__device__ __half g_xh [MQ*DD];         // fp16 copy (GEMM input)
__device__ float  g_qh [BHH*SS*HDIM];
__device__ float  g_kh [BHH*SS*HDIM];
__device__ float  g_vh [BHH*SS*HDIM];
__device__ __half g_att[MQ*DD];         // flash output (fp16, GEMM input)
__device__ float  g_y  [MQ*DD];
__device__ __half g_ff [MQ*FFD];        // relu output (fp16, GEMM input)
__device__ float  g_dec [MDEC*DD];      // exact (softmax input)
__device__ __half g_dech[MDEC*DD];      // fp16 (GEMM input)
__device__ __half g_fvh[MKV*DD];

// fp16 weights
__device__ __half g_w_selfin [NL*3*DD*DD];
__device__ __half g_w_selfout[NL*DD*DD];
__device__ __half g_w_crossin[NL*3*DD*DD];
__device__ __half g_w_crossout[NL*DD*DD];
__device__ __half g_w_lin1   [NL*FFD*DD];
__device__ __half g_w_lin2   [NL*DD*FFD];
__device__ __half g_w_fc     [VOC*DD];

// ---------------- reductions (256-thread blocks) ----------------
__device__ __forceinline__ float blk_sum256(float v) {
    __shared__ float sh[8];
    #pragma unroll
    for (int o = 16; o > 0; o >>= 1) v += __shfl_xor_sync(0xffffffffu, v, o);
    __syncthreads();
    if ((threadIdx.x & 31) == 0) sh[threadIdx.x >> 5] = v;
    __syncthreads();
    float r = sh[0];
    #pragma unroll
    for (int i = 1; i < 8; i++) r += sh[i];
    return r;
}

__device__ __forceinline__ float blk_max256(float v) {
    __shared__ float sh[8];
    #pragma unroll
    for (int o = 16; o > 0; o >>= 1) v = fmaxf(v, __shfl_xor_sync(0xffffffffu, v, o));
    __syncthreads();
    if ((threadIdx.x & 31) == 0) sh[threadIdx.x >> 5] = v;
    __syncthreads();
    float r = sh[0];
    #pragma unroll
    for (int i = 1; i < 8; i++) r = fmaxf(r, sh[i]);
    return r;
}

// ---------------- mma helpers ----------------
__device__ __forceinline__ unsigned f2tf32(float f) {
    unsigned u;
    asm("cvt.rna.tf32.f32 %0, %1;" : "=r"(u) : "f"(f));
    return u;
}

__device__ __forceinline__ void mma_f16(float (&d)[4], const unsigned (&a)[4], const unsigned (&b)[2]) {
    asm volatile(
        "mma.sync.aligned.m16n8k16.row.col.f32.f16.f16.f32 "
        "{%0,%1,%2,%3}, {%4,%5,%6,%7}, {%8,%9}, {%0,%1,%2,%3};\n"
        : "+f"(d[0]), "+f"(d[1]), "+f"(d[2]), "+f"(d[3])
        : "r"(a[0]), "r"(a[1]), "r"(a[2]), "r"(a[3]), "r"(b[0]), "r"(b[1]));
}

__device__ __forceinline__ void mma_tf32(float (&d)[4], const unsigned (&a)[4], const unsigned (&b)[2]) {
    asm volatile(
        "mma.sync.aligned.m16n8k8.row.col.f32.tf32.tf32.f32 "
        "{%0,%1,%2,%3}, {%4,%5,%6,%7}, {%8,%9}, {%0,%1,%2,%3};\n"
        : "+f"(d[0]), "+f"(d[1]), "+f"(d[2]), "+f"(d[3])
        : "r"(a[0]), "r"(a[1]), "r"(a[2]), "r"(a[3]), "r"(b[0]), "r"(b[1]));
}

__device__ __forceinline__ void ldsm4(unsigned &d0, unsigned &d1, unsigned &d2, unsigned &d3, uint32_t a) {
    asm volatile("ldmatrix.sync.aligned.m8n8.x4.shared.b16 {%0,%1,%2,%3}, [%4];"
                 : "=r"(d0), "=r"(d1), "=r"(d2), "=r"(d3) : "r"(a));
}

__device__ __forceinline__ uint32_t smem_u32(const void* p) {
    uint32_t a;
    asm("{ .reg .u64 t; cvta.to.shared.u64 t, %1; cvt.u32.u64 %0, t; }" : "=r"(a) : "l"(p));
    return a;
}

__device__ __forceinline__ void cp16(uint32_t dst, const void* src, bool pred) {
    int sz = pred ? 16 : 0;
    asm volatile("cp.async.cg.shared.global [%0], [%1], 16, %2;" :: "r"(dst), "l"(src), "r"(sz));
}
#define CP_COMMIT() asm volatile("cp.async.commit_group;" ::: "memory")
#define CP_WAIT1()  asm volatile("cp.async.wait_group 1;" ::: "memory")

// ---------------- fp32 -> fp16 conversion pass ----------------
__global__ void cvt_h_kernel(const float4* __restrict__ in, uint2* __restrict__ out, int n4) {
    int i = blockIdx.x*blockDim.x + threadIdx.x;
    int stride = gridDim.x*blockDim.x;
    for (; i < n4; i += stride) {
        float4 v = in[i];
        __half2 h0 = __floats2half2_rn(v.x, v.y);
        __half2 h1 = __floats2half2_rn(v.z, v.w);
        out[i] = make_uint2(*(uint32_t*)&h0, *(uint32_t*)&h1);
    }
}

// ---------------- main dense GEMM (fp16 mma m16n8k16, cp.async 3-stage) ----------------
// C[M,N] = A[M,K] * B[N,K]^T (+bias).  A,B fp16.  K % 32 == 0, K/32 >= 2.
// mode 0: row-major out -> float C, or (relu+)half Ch if Ch != null.
// mode 1: QKV pack. 2: Q pack. 3: KV pack (float outputs).
#define SKH 40                         // smem row stride in halves (80 B, ldmatrix conflict-free)
#define STG_B (128*SKH*2*2)            // bytes per stage (A+B) = 20480
#define GEMM_DSMEM (3*STG_B)           // 61440

__global__ __launch_bounds__(256, 2) void gemm_nt_f16(
    const __half* __restrict__ A, const __half* __restrict__ Bm,
    const float* __restrict__ bias, float* __restrict__ C, __half* __restrict__ Ch,
    int M, int N, int K, int relu, int mode,
    float* __restrict__ dq, float* __restrict__ dk, float* __restrict__ dv)
{
    extern __shared__ unsigned sm[];
    const uint32_t sb = smem_u32(sm);
    const int tid  = threadIdx.x;
    const int lane = tid & 31;
    const int wid  = tid >> 5;
    const int m0   = blockIdx.y * 128;
    const int n0   = blockIdx.x * 128;
    const int wm   = (wid & 3) * 32;
    const int wn   = (wid >> 2) * 64;
    const int g    = lane >> 2;
    const int t    = lane & 3;

    // ldmatrix per-lane byte offsets
    const uint32_t aoffB = (uint32_t)((((lane & 7) + ((lane >> 3) & 1)*8)*SKH + ((lane >> 4) & 1)*8) * 2);
    const uint32_t boffB = (uint32_t)((((lane & 7) + ((lane >> 4) & 1)*8)*SKH + ((lane >> 3) & 1)*8) * 2);

    const int lrow = tid >> 1;          // 0..127
    const int segb = (tid & 1) * 2;     // 0 or 2

    float acc[2][8][4];
    #pragma unroll
    for (int mi = 0; mi < 2; mi++)
        #pragma unroll
        for (int ni = 0; ni < 8; ni++)
            #pragma unroll
            for (int e = 0; e < 4; e++) acc[mi][ni][e] = 0.f;

    const int NC = K >> 5;

    // prologue: issue chunks 0,1
    #pragma unroll
    for (int pc = 0; pc < 2; pc++) {
        const int k0 = pc << 5;
        const uint32_t sA = sb + (uint32_t)(pc * STG_B);
        const uint32_t sB = sA + (uint32_t)(128*SKH*2);
        #pragma unroll
        for (int e = 0; e < 2; e++) {
            int seg = segb + e;
            int gm = m0 + lrow;
            cp16(sA + (uint32_t)(lrow*SKH*2 + seg*16),
                 A + (size_t)(gm < M ? gm : 0)*K + k0 + seg*8, gm < M);
            int gn = n0 + lrow;
            cp16(sB + (uint32_t)(lrow*SKH*2 + seg*16),
                 Bm + (size_t)(gn < N ? gn : 0)*K + k0 + seg*8, gn < N);
        }
        CP_COMMIT();
    }

    for (int c = 0; c < NC; c++) {
        CP_WAIT1();
        __syncthreads();

        if (c + 2 < NC) {
            const int k0 = (c + 2) << 5;
            const int s = (c + 2) % 3;
            const uint32_t sA = sb + (uint32_t)(s * STG_B);
            const uint32_t sB = sA + (uint32_t)(128*SKH*2);
            #pragma unroll
            for (int e = 0; e < 2; e++) {
                int seg = segb + e;
                int gm = m0 + lrow;
                cp16(sA + (uint32_t)(lrow*SKH*2 + seg*16),
                     A + (size_t)(gm < M ? gm : 0)*K + k0 + seg*8, gm < M);
                int gn = n0 + lrow;
                cp16(sB + (uint32_t)(lrow*SKH*2 + seg*16),
                     Bm + (size_t)(gn < N ? gn : 0)*K + k0 + seg*8, gn < N);
            }
        }
        CP_COMMIT();

        const int s = c % 3;
        const uint32_t Acur = sb + (uint32_t)(s * STG_B);
        const uint32_t Bcur = Acur + (uint32_t)(128*SKH*2);
        #pragma unroll
        for (int ks = 0; ks < 2; ks++) {
            unsigned a[2][4], b[8][2];
            #pragma unroll
            for (int mi = 0; mi < 2; mi++)
                ldsm4(a[mi][0], a[mi][1], a[mi][2], a[mi][3],
                      Acur + (uint32_t)(((wm + mi*16)*SKH + ks*16)*2) + aoffB);
            #pragma unroll
            for (int nj = 0; nj < 4; nj++)
                ldsm4(b[2*nj][0], b[2*nj][1], b[2*nj+1][0], b[2*nj+1][1],
                      Bcur + (uint32_t)(((wn + nj*16)*SKH + ks*16)*2) + boffB);
            #pragma unroll
            for (int mi = 0; mi < 2; mi++)
                #pragma unroll
                for (int ni = 0; ni < 8; ni++)
                    mma_f16(acc[mi][ni], a[mi], b[ni]);
        }
    }

    // ---- epilogue ----
    #pragma unroll
    for (int mi = 0; mi < 2; mi++) {
        #pragma unroll
        for (int half_ = 0; half_ < 2; half_++) {
            int r = m0 + wm + mi*16 + g + half_*8;
            if (r >= M) continue;
            #pragma unroll
            for (int ni = 0; ni < 8; ni++) {
                int cn = n0 + wn + ni*8 + 2*t;
                if (cn >= N) continue;
                float v0 = acc[mi][ni][half_*2 + 0];
                float v1 = acc[mi][ni][half_*2 + 1];
                if (bias) { v0 += bias[cn]; if (cn+1 < N) v1 += bias[cn+1]; }
                if (mode == 0) {
                    if (relu) { v0 = fmaxf(v0, 0.f); v1 = fmaxf(v1, 0.f); }
                    if (Ch) {
                        __half2 hv = __floats2half2_rn(v0, v1);
                        if (cn + 1 < N) *(__half2*)(Ch + (size_t)r*N + cn) = hv;
                        else            Ch[(size_t)r*N + cn] = __float2half(v0);
                    } else {
                        if (cn + 1 < N) *(float2*)(C + (size_t)r*N + cn) = make_float2(v0, v1);
                        else            C[(size_t)r*N + cn] = v0;
                    }
                } else {
                    int bb_, s_, which, rem, hh, dd;
                    float* base;
                    if (mode == 1) {
                        bb_ = r >> 8; s_ = r & 255;
                        which = cn / DD; rem = cn - which*DD;
                        hh = rem / HDIM; dd = rem - hh*HDIM;
                        base = (which == 0) ? dq : (which == 1) ? dk : dv;
                        base += (((size_t)((bb_<<3) + hh))*SS + s_)*HDIM + dd;
                    } else if (mode == 2) {
                        bb_ = r >> 8; s_ = r & 255;
                        hh = cn / HDIM; dd = cn - hh*HDIM;
                        base = dq + (((size_t)((bb_<<3) + hh))*SS + s_)*HDIM + dd;
                    } else {
                        bb_ = r / NVV; s_ = r - bb_*NVV;
                        which = cn / DD; rem = cn - which*DD;
                        hh = rem / HDIM; dd = rem - hh*HDIM;
                        base = ((which == 0) ? dk : dv);
                        base += (((size_t)((bb_<<3) + hh))*NVV + s_)*HDIM + dd;
                    }
                    *(float2*)base = make_float2(v0, v1);
                }
            }
        }
    }
}

// ---------------- fused flash attention (tf32 mma, fp16 output) ----------------
#define FA_SP  36
#define FA_SKK 100

__global__ __launch_bounds__(256) void flash_attn(
    const float* __restrict__ Qh, const float* __restrict__ Kh, const float* __restrict__ Vh,
    __half* __restrict__ Oatt, int kvlen, int causal)
{
    __shared__ unsigned Ks[32*FA_SKK];
    __shared__ unsigned Vs[96*FA_SP];
    __shared__ unsigned Ps[8][16*FA_SP];
    const int tid = threadIdx.x, w = tid >> 5, lane = tid & 31;
    const int g = lane >> 2, t = lane & 3;
    const int z = blockIdx.y;
    const int b = z >> 3, h = z & 7;
    const int q0 = blockIdx.x * 128;
    const float scale = 0.1020620726159658f;   // 1/sqrt(96)

    const float* Qb = Qh + ((size_t)z*SS + q0)*HDIM;
    const float* Kb = Kh + (size_t)z*kvlen*HDIM;
    const float* Vb = Vh + (size_t)z*kvlen*HDIM;

    unsigned qa[12][4];
    {
        const float* qr0 = Qb + (w*16 + g)*HDIM;
        const float* qr1 = qr0 + 8*HDIM;
        #pragma unroll
        for (int ks = 0; ks < 12; ks++) {
            qa[ks][0] = f2tf32(qr0[ks*8 + t] * scale);
            qa[ks][1] = f2tf32(qr1[ks*8 + t] * scale);
            qa[ks][2] = f2tf32(qr0[ks*8 + t + 4] * scale);
            qa[ks][3] = f2tf32(qr1[ks*8 + t + 4] * scale);
        }
    }

    float oacc[12][4];
    #pragma unroll
    for (int n = 0; n < 12; n++) { oacc[n][0]=0.f; oacc[n][1]=0.f; oacc[n][2]=0.f; oacc[n][3]=0.f; }
    float m0 = -1e30f, m1 = -1e30f, l0 = 0.f, l1 = 0.f;
    const int row0 = q0 + w*16 + g;
    const int row1 = row0 + 8;

    const uint32_t KsA = smem_u32(Ks);
    const uint32_t VsA = smem_u32(Vs);
    const uint32_t PsA = smem_u32(Ps[w]);
    const int boffK = ((lane & 7) + ((lane >> 4) & 1)*8)*FA_SKK + ((lane >> 3) & 1)*4;
    const int boffV = ((lane & 7) + ((lane >> 4) & 1)*8)*FA_SP  + ((lane >> 3) & 1)*4;
    const int aoffP = ((lane & 7) + ((lane >> 3) & 1)*8)*FA_SP  + ((lane >> 4) & 1)*4;

    int ntiles = (kvlen + 31) >> 5;
    if (causal) { int lim = ((q0 + 127) >> 5) + 1; if (lim < ntiles) ntiles = lim; }

    for (int j = 0; j < ntiles; j++) {
        const int k0 = j*32;

        #pragma unroll
        for (int it = 0; it < 3; it++) {
            int idx = it*256 + tid;
            int key = idx / 24, q = idx - key*24;
            float4 v = make_float4(0.f,0.f,0.f,0.f);
            if (k0 + key < kvlen) v = *(const float4*)(Kb + (size_t)(k0+key)*HDIM + q*4);
            unsigned* dst = &Ks[key*FA_SKK + q*4];
            dst[0] = f2tf32(v.x); dst[1] = f2tf32(v.y); dst[2] = f2tf32(v.z); dst[3] = f2tf32(v.w);
        }
        #pragma unroll
        for (int it = 0; it < 3; it++) {
            int idx = it*256 + tid;
            int key = idx & 31, dq4 = idx >> 5;
            float4 v = make_float4(0.f,0.f,0.f,0.f);
            if (k0 + key < kvlen) v = *(const float4*)(Vb + (size_t)(k0+key)*HDIM + dq4*4);
            Vs[(dq4*4+0)*FA_SP + key] = f2tf32(v.x);
            Vs[(dq4*4+1)*FA_SP + key] = f2tf32(v.y);
            Vs[(dq4*4+2)*FA_SP + key] = f2tf32(v.z);
            Vs[(dq4*4+3)*FA_SP + key] = f2tf32(v.w);
        }
        __syncthreads();

        const bool active = !(causal && k0 > q0 + w*16 + 15);
        if (active) {
            float sacc[4][4];
            #pragma unroll
            for (int n = 0; n < 4; n++) { sacc[n][0]=0.f; sacc[n][1]=0.f; sacc[n][2]=0.f; sacc[n][3]=0.f; }
            #pragma unroll
            for (int ks = 0; ks < 12; ks++) {
                unsigned bb[4][2];
                ldsm4(bb[0][0], bb[0][1], bb[1][0], bb[1][1],
                      KsA + (uint32_t)((ks*8 + boffK) * 4));
                ldsm4(bb[2][0], bb[2][1], bb[3][0], bb[3][1],
                      KsA + (uint32_t)((16*FA_SKK + ks*8 + boffK) * 4));
                #pragma unroll
                for (int n = 0; n < 4; n++) mma_tf32(sacc[n], qa[ks], bb[n]);
            }

            const bool need_mask = causal || (k0 + 31 >= kvlen);
            if (need_mask) {
                #pragma unroll
                for (int n = 0; n < 4; n++) {
                    int colb = k0 + n*8 + 2*t;
                    #pragma unroll
                    for (int e = 0; e < 4; e++) {
                        int col = colb + (e & 1);
                        int row = (e < 2) ? row0 : row1;
                        if (col >= kvlen || (causal && col > row)) sacc[n][e] = -1e9f;
                    }
                }
            }

            float tm0 = fmaxf(fmaxf(sacc[0][0], sacc[0][1]), fmaxf(sacc[1][0], sacc[1][1]));
            tm0 = fmaxf(tm0, fmaxf(fmaxf(sacc[2][0], sacc[2][1]), fmaxf(sacc[3][0], sacc[3][1])));
            float tm1 = fmaxf(fmaxf(sacc[0][2], sacc[0][3]), fmaxf(sacc[1][2], sacc[1][3]));
            tm1 = fmaxf(tm1, fmaxf(fmaxf(sacc[2][2], sacc[2][3]), fmaxf(sacc[3][2], sacc[3][3])));
            tm0 = fmaxf(tm0, __shfl_xor_sync(0xffffffffu, tm0, 1));
            tm0 = fmaxf(tm0, __shfl_xor_sync(0xffffffffu, tm0, 2));
            tm1 = fmaxf(tm1, __shfl_xor_sync(0xffffffffu, tm1, 1));
            tm1 = fmaxf(tm1, __shfl_xor_sync(0xffffffffu, tm1, 2));
            float mn0 = fmaxf(m0, tm0), mn1 = fmaxf(m1, tm1);
            float a0 = __expf(m0 - mn0), a1 = __expf(m1 - mn1);
            float rs0 = 0.f, rs1 = 0.f;
            #pragma unroll
            for (int n = 0; n < 4; n++) {
                sacc[n][0] = __expf(sacc[n][0] - mn0); rs0 += sacc[n][0];
                sacc[n][1] = __expf(sacc[n][1] - mn0); rs0 += sacc[n][1];
                sacc[n][2] = __expf(sacc[n][2] - mn1); rs1 += sacc[n][2];
                sacc[n][3] = __expf(sacc[n][3] - mn1); rs1 += sacc[n][3];
            }
            rs0 += __shfl_xor_sync(0xffffffffu, rs0, 1);
            rs0 += __shfl_xor_sync(0xffffffffu, rs0, 2);
            rs1 += __shfl_xor_sync(0xffffffffu, rs1, 1);
            rs1 += __shfl_xor_sync(0xffffffffu, rs1, 2);
            l0 = l0*a0 + rs0; l1 = l1*a1 + rs1;
            m0 = mn0; m1 = mn1;
            #pragma unroll
            for (int n = 0; n < 12; n++) {
                oacc[n][0] *= a0; oacc[n][1] *= a0;
                oacc[n][2] *= a1; oacc[n][3] *= a1;
            }

            #pragma unroll
            for (int n = 0; n < 4; n++) {
                uint32_t ad0 = PsA + (uint32_t)(((g    )*FA_SP + n*8 + 2*t) * 4);
                uint32_t ad1 = PsA + (uint32_t)(((g + 8)*FA_SP + n*8 + 2*t) * 4);
                unsigned p0 = f2tf32(sacc[n][0]), p1 = f2tf32(sacc[n][1]);
                unsigned p2 = f2tf32(sacc[n][2]), p3 = f2tf32(sacc[n][3]);
                asm volatile("st.shared.v2.b32 [%0], {%1,%2};" :: "r"(ad0), "r"(p0), "r"(p1) : "memory");
                asm volatile("st.shared.v2.b32 [%0], {%1,%2};" :: "r"(ad1), "r"(p2), "r"(p3) : "memory");
            }
            __syncwarp();

            #pragma unroll
            for (int ks = 0; ks < 4; ks++) {
                unsigned pa[4];
                ldsm4(pa[0], pa[1], pa[2], pa[3], PsA + (uint32_t)((ks*8 + aoffP) * 4));
                unsigned vb[12][2];
                #pragma unroll
                for (int nj = 0; nj < 6; nj++)
                    ldsm4(vb[2*nj][0], vb[2*nj][1], vb[2*nj+1][0], vb[2*nj+1][1],
                          VsA + (uint32_t)((nj*16*FA_SP + ks*8 + boffV) * 4));
                #pragma unroll
                for (int n = 0; n < 12; n++) mma_tf32(oacc[n], pa, vb[n]);
            }
        }
        __syncthreads();
    }

    float inv0 = 1.f / l0, inv1 = 1.f / l1;
    __half* o0 = Oatt + ((size_t)(b*SS + row0))*DD + h*HDIM;
    __half* o1 = o0 + (size_t)8*DD;
    #pragma unroll
    for (int n = 0; n < 12; n++) {
        int cc = n*8 + 2*t;
        *(__half2*)(o0 + cc) = __floats2half2_rn(oacc[n][0]*inv0, oacc[n][1]*inv0);
        *(__half2*)(o1 + cc) = __floats2half2_rn(oacc[n][2]*inv1, oacc[n][3]*inv1);
    }
}

// ---------------- elementwise / softmax / LN ----------------
__global__ void add_pe_kernel(const float* __restrict__ te) {
    int idx = blockIdx.x*blockDim.x + threadIdx.x;
    if (idx >= MQ*DD) return;
    int d = idx % DD;
    int s = (idx / DD) % SS;
    int i2 = d & ~1;
    const float kfac = 9.210340371976184f / (float)DD;
    float div = expf(-(float)i2 * kfac);
    float ang = (float)s * div;
    float pe = (d & 1) ? cosf(ang) : sinf(ang);
    float v = te[idx] + pe;
    g_x[idx] = v;
    g_xh[idx] = __float2half(v);
}

__global__ __launch_bounds__(256) void add_ln_kernel(const float* __restrict__ y,
                                                     const float* __restrict__ w,
                                                     const float* __restrict__ b) {
    int r = blockIdx.x;
    int t = threadIdx.x;
    float vs[3];
    float s = 0.f;
    #pragma unroll
    for (int i = 0; i < 3; i++) {
        int c = t + i*256;
        vs[i] = g_x[(size_t)r*DD + c] + y[(size_t)r*DD + c];
        s += vs[i];
    }
    float mean = blk_sum256(s) * (1.f/DD);
    float ss = 0.f;
    #pragma unroll
    for (int i = 0; i < 3; i++) { float d0 = vs[i] - mean; ss += d0*d0; }
    float var = blk_sum256(ss) * (1.f/DD);
    float inv = rsqrtf(var + 1e-5f);
    #pragma unroll
    for (int i = 0; i < 3; i++) {
        int c = t + i*256;
        float o = (vs[i] - mean)*inv*w[c] + b[c];
        g_x[(size_t)r*DD + c] = o;
        g_xh[(size_t)r*DD + c] = __float2half(o);
    }
}

__global__ __launch_bounds__(256) void softmax_d_kernel(float* __restrict__ out) {
    int r = blockIdx.x;
    int t = threadIdx.x;
    const float* p = g_dec + (size_t)r*DD;
    float vs[3]; float m = -3.0e38f;
    #pragma unroll
    for (int i = 0; i < 3; i++) { vs[i] = p[t + i*256]; m = fmaxf(m, vs[i]); }
    float mx = blk_max256(m);
    float s = 0.f;
    #pragma unroll
    for (int i = 0; i < 3; i++) { vs[i] = expf(vs[i] - mx); s += vs[i]; }
    float sum = blk_max256(0.f) * 0.f + blk_sum256(s);
    #pragma unroll
    for (int i = 0; i < 3; i++)
        out[(size_t)r*DD + t + i*256] = vs[i] / sum;
}

__global__ void copy_dec_kernel() {
    int idx = blockIdx.x*blockDim.x + threadIdx.x;
    if (idx >= MDEC*DD) return;
    int c = idx % DD;
    int r = idx / DD;
    int b = r / (SS-1);
    int s = r % (SS-1);
    float v = g_x[((size_t)(b*SS + s))*DD + c];
    g_dec[idx] = v;
    g_dech[idx] = __float2half(v);
}

// ---------------- host orchestration ----------------
static inline dim3 gemm_grid(int M, int N) { return dim3((N + 127)/128, (M + 127)/128); }

static void cvt_arr(const float* src, __half* dst, size_t n) {
    int n4 = (int)(n >> 2);
    int blocks = (n4 + 255)/256;
    if (blocks > 8192) blocks = 8192;
    cvt_h_kernel<<<blocks, 256>>>((const float4*)src, (uint2*)dst, n4);
}

extern "C" void kernel_launch(void* const* d_in, const int* in_sizes, int n_in,
                              void* d_out, int out_size) {
    (void)in_sizes; (void)n_in; (void)out_size;
    const float* fv          = (const float*)d_in[0];
    const float* te          = (const float*)d_in[1];
    const float* self_in_w   = (const float*)d_in[2];
    const float* self_in_b   = (const float*)d_in[3];
    const float* self_out_w  = (const float*)d_in[4];
    const float* self_out_b  = (const float*)d_in[5];
    const float* cross_in_w  = (const float*)d_in[6];
    const float* cross_in_b  = (const float*)d_in[7];
    const float* cross_out_w = (const float*)d_in[8];
    const float* cross_out_b = (const float*)d_in[9];
    const float* lin1_w      = (const float*)d_in[10];
    const float* lin1_b      = (const float*)d_in[11];
    const float* lin2_w      = (const float*)d_in[12];
    const float* lin2_b      = (const float*)d_in[13];
    const float* ln_w        = (const float*)d_in[14];
    const float* ln_b        = (const float*)d_in[15];
    const float* fc_out_w    = (const float*)d_in[16];
    float* out = (float*)d_out;

    cudaFuncSetAttribute(gemm_nt_f16, cudaFuncAttributeMaxDynamicSharedMemorySize, GEMM_DSMEM);

    float *x, *qh, *kh, *vh, *y, *dec;
    __half *xh, *att, *ff, *dech, *fvh;
    __half *wsi, *wso, *wci, *wco, *wl1, *wl2, *wfc;
    cudaGetSymbolAddress((void**)&x,    g_x);
    cudaGetSymbolAddress((void**)&xh,   g_xh);
    cudaGetSymbolAddress((void**)&qh,   g_qh);
    cudaGetSymbolAddress((void**)&kh,   g_kh);
    cudaGetSymbolAddress((void**)&vh,   g_vh);
    cudaGetSymbolAddress((void**)&att,  g_att);
    cudaGetSymbolAddress((void**)&y,    g_y);
    cudaGetSymbolAddress((void**)&ff,   g_ff);
    cudaGetSymbolAddress((void**)&dec,  g_dec);
    cudaGetSymbolAddress((void**)&dech, g_dech);
    cudaGetSymbolAddress((void**)&fvh,  g_fvh);
    cudaGetSymbolAddress((void**)&wsi,  g_w_selfin);
    cudaGetSymbolAddress((void**)&wso,  g_w_selfout);
    cudaGetSymbolAddress((void**)&wci,  g_w_crossin);
    cudaGetSymbolAddress((void**)&wco,  g_w_crossout);
    cudaGetSymbolAddress((void**)&wl1,  g_w_lin1);
    cudaGetSymbolAddress((void**)&wl2,  g_w_lin2);
    cudaGetSymbolAddress((void**)&wfc,  g_w_fc);

    // convert all weights + fv to fp16 once
    cvt_arr(self_in_w,   wsi, (size_t)NL*3*DD*DD);
    cvt_arr(self_out_w,  wso, (size_t)NL*DD*DD);
    cvt_arr(cross_in_w,  wci, (size_t)NL*3*DD*DD);
    cvt_arr(cross_out_w, wco, (size_t)NL*DD*DD);
    cvt_arr(lin1_w,      wl1, (size_t)NL*FFD*DD);
    cvt_arr(lin2_w,      wl2, (size_t)NL*DD*FFD);
    cvt_arr(fc_out_w,    wfc, (size_t)VOC*DD);
    cvt_arr(fv,          fvh, (size_t)MKV*DD);

    add_pe_kernel<<<(MQ*DD + 255)/256, 256>>>(te);

    for (int l = 0; l < NL; l++) {
        const __half* siw = wsi + (size_t)l*3*DD*DD;
        const float*  sib = self_in_b   + (size_t)l*3*DD;
        const __half* sow = wso + (size_t)l*DD*DD;
        const float*  sob = self_out_b  + (size_t)l*DD;
        const __half* ciw = wci + (size_t)l*3*DD*DD;
        const float*  cib = cross_in_b  + (size_t)l*3*DD;
        const __half* cow = wco + (size_t)l*DD*DD;
        const float*  cob = cross_out_b + (size_t)l*DD;
        const __half* l1w = wl1 + (size_t)l*FFD*DD;
        const float*  l1b = lin1_b + (size_t)l*FFD;
        const __half* l2w = wl2 + (size_t)l*DD*FFD;
        const float*  l2b = lin2_b + (size_t)l*DD;

        // ---- self attention ----
        gemm_nt_f16<<<gemm_grid(MQ, 3*DD), 256, GEMM_DSMEM>>>(xh, siw, sib, nullptr, nullptr, MQ, 3*DD, DD, 0, 1, qh, kh, vh);
        flash_attn<<<dim3(SS/128, BHH), 256>>>(qh, kh, vh, att, SS, 1);
        gemm_nt_f16<<<gemm_grid(MQ, DD), 256, GEMM_DSMEM>>>(att, sow, sob, y, nullptr, MQ, DD, DD, 0, 0, nullptr, nullptr, nullptr);
        add_ln_kernel<<<MQ, 256>>>(y, ln_w + (size_t)(l*3 + 0)*DD, ln_b + (size_t)(l*3 + 0)*DD);

        // ---- cross attention ----
        gemm_nt_f16<<<gemm_grid(MQ, DD), 256, GEMM_DSMEM>>>(xh, ciw, cib, nullptr, nullptr, MQ, DD, DD, 0, 2, qh, nullptr, nullptr);
        gemm_nt_f16<<<gemm_grid(MKV, 2*DD), 256, GEMM_DSMEM>>>(fvh, ciw + (size_t)DD*DD, cib + DD, nullptr, nullptr,
                                                               MKV, 2*DD, DD, 0, 3, nullptr, kh, vh);
        flash_attn<<<dim3(SS/128, BHH), 256>>>(qh, kh, vh, att, NVV, 0);
        gemm_nt_f16<<<gemm_grid(MQ, DD), 256, GEMM_DSMEM>>>(att, cow, cob, y, nullptr, MQ, DD, DD, 0, 0, nullptr, nullptr, nullptr);
        add_ln_kernel<<<MQ, 256>>>(y, ln_w + (size_t)(l*3 + 1)*DD, ln_b + (size_t)(l*3 + 1)*DD);

        // ---- FFN ----
        gemm_nt_f16<<<gemm_grid(MQ, FFD), 256, GEMM_DSMEM>>>(xh, l1w, l1b, nullptr, ff, MQ, FFD, DD, 1, 0, nullptr, nullptr, nullptr);
        gemm_nt_f16<<<gemm_grid(MQ, DD), 256, GEMM_DSMEM>>>(ff, l2w, l2b, y, nullptr, MQ, DD, FFD, 0, 0, nullptr, nullptr, nullptr);
        add_ln_kernel<<<MQ, 256>>>(y, ln_w + (size_t)(l*3 + 2)*DD, ln_b + (size_t)(l*3 + 2)*DD);
    }

    // ---- outputs: logits then F_t ----
    copy_dec_kernel<<<(MDEC*DD + 255)/256, 256>>>();
    gemm_nt_f16<<<gemm_grid(MDEC, VOC), 256, GEMM_DSMEM>>>(dech, wfc, nullptr, out, nullptr, MDEC, VOC, DD, 0, 0, nullptr, nullptr, nullptr);
    softmax_d_kernel<<<MDEC, 256>>>(out + (size_t)MDEC*VOC);
}